// round 10
// baseline (speedup 1.0000x reference)
#include <cuda_runtime.h>
#include <cuda_fp16.h>
#include <cstdint>

#define SLEN    2048
#define DMODEL  1024
#define NHEAD   16
#define DKH     64
#define NB      4
#define MTOT    (NB * SLEN)     // 8192

// ---------------- scratch (allocation-free: __device__ globals) ----------------
// pre-split fp16 hi/lo Q/K/V, layout [B,H,S,64].
// Q is pre-scaled by 0.125*log2(e); Q and K are d-PAIR-PERMUTED; V is natural.
__device__ __half g_Qh[(size_t)NB * NHEAD * SLEN * DKH];
__device__ __half g_Ql[(size_t)NB * NHEAD * SLEN * DKH];
__device__ __half g_Kh[(size_t)NB * NHEAD * SLEN * DKH];
__device__ __half g_Kl[(size_t)NB * NHEAD * SLEN * DKH];
__device__ __half g_Vh[(size_t)NB * NHEAD * SLEN * DKH];
__device__ __half g_Vl[(size_t)NB * NHEAD * SLEN * DKH];

// pre-converted tf32 operands, pair-permuted within each 8-k group
__device__ uint32_t g_Xt[(size_t)3 * MTOT * DMODEL];     // q,k,v inputs
__device__ uint32_t g_Wt[(size_t)4 * DMODEL * DMODEL];   // wq,wk,wv,wo
__device__ uint32_t g_AOt[(size_t)MTOT * DMODEL];        // attn out, tf32 permuted

// ---------------- helpers ------------------------------------------------------
__device__ __forceinline__ uint32_t f2tf32(float f) {
    uint32_t u;
    asm("cvt.rna.tf32.f32 %0, %1;" : "=r"(u) : "f"(f));
    return u;
}

__device__ __forceinline__ void mma_tf32(float c[4], const uint32_t a[4], const uint32_t b[2]) {
    asm volatile(
        "mma.sync.aligned.m16n8k8.row.col.f32.tf32.tf32.f32 "
        "{%0,%1,%2,%3}, {%4,%5,%6,%7}, {%8,%9}, {%0,%1,%2,%3};"
        : "+f"(c[0]), "+f"(c[1]), "+f"(c[2]), "+f"(c[3])
        : "r"(a[0]), "r"(a[1]), "r"(a[2]), "r"(a[3]), "r"(b[0]), "r"(b[1]));
}

__device__ __forceinline__ uint32_t smem_u32(const void* p) {
    uint32_t a;
    asm("{ .reg .u64 t; cvta.to.shared.u64 t, %1; cvt.u32.u64 %0, t; }" : "=r"(a) : "l"(p));
    return a;
}

__device__ __forceinline__ void cp16(uint32_t dst, const void* src) {
    asm volatile("cp.async.cg.shared.global [%0], [%1], 16;" :: "r"(dst), "l"(src));
}
#define CP_COMMIT() asm volatile("cp.async.commit_group;")
#define CP_WAIT(n)  asm volatile("cp.async.wait_group %0;" :: "n"(n))

__device__ __forceinline__ uint2 ldsm_x2_trans(uint32_t addr) {
    uint2 r;
    asm volatile("ldmatrix.sync.aligned.m8n8.x2.trans.shared.b16 {%0,%1}, [%2];"
                 : "=r"(r.x), "=r"(r.y) : "r"(addr));
    return r;
}

// ---------------- fused tf32 pre-convert (all 7 tensors, one launch) -----------
__global__ __launch_bounds__(256) void conv_all_kernel(
    const float* __restrict__ q, const float* __restrict__ k, const float* __restrict__ v,
    const float* __restrict__ wq, const float* __restrict__ wk,
    const float* __restrict__ wv, const float* __restrict__ wo)
{
    int b = blockIdx.x;
    const float* src;
    uint32_t* dst;
    int i;
    if (b < 12288) {
        int sel = b >> 12;
        src = (sel == 0) ? q : (sel == 1) ? k : v;
        dst = g_Xt + (size_t)sel * MTOT * DMODEL;
        i = (b & 4095) * 256 + threadIdx.x;
    } else {
        int sel = (b - 12288) >> 9;
        src = (sel == 0) ? wq : (sel == 1) ? wk : (sel == 2) ? wv : wo;
        dst = g_Wt + (size_t)sel * DMODEL * DMODEL;
        i = ((b - 12288) & 511) * 256 + threadIdx.x;
    }
    const float4* s4 = (const float4*)src;
    uint4* d4 = (uint4*)dst;
    float4 v0 = s4[2 * i];
    float4 v1 = s4[2 * i + 1];
    uint4 o0, o1;
    o0.x = f2tf32(v0.x); o0.y = f2tf32(v1.x);
    o0.z = f2tf32(v0.y); o0.w = f2tf32(v1.y);
    o1.x = f2tf32(v0.z); o1.y = f2tf32(v1.z);
    o1.z = f2tf32(v0.w); o1.w = f2tf32(v1.w);
    d4[2 * i]     = o0;
    d4[2 * i + 1] = o1;
}

// ======================= tf32 tensor-core GEMM =================================
// 256x128 CTA tile, 512 threads (4m x 4n warps, warp tile 64x32), BK=32, 2-stage.
#define BK2 32
#define P40 40
#define A_STAGEU (256 * P40)                  // 10240 u32
#define B_STAGEU (128 * P40)                  // 5120 u32
#define STAGEU   (A_STAGEU + B_STAGEU)        // 15360 u32
#define GEMM_SMEM (2 * STAGEU * 4)            // 122880 bytes

__device__ __forceinline__ void gemm_tf32_main(const uint32_t* __restrict__ X,
                                               const uint32_t* __restrict__ W,
                                               int m0, int n0,
                                               float acc[4][4][4]) {
    extern __shared__ uint32_t su[];
    const int tid  = threadIdx.x;
    const int lane = tid & 31, warp = tid >> 5;
    const int wm = warp >> 2, wn = warp & 3;     // 4m x 4n
    const int g  = lane >> 2, tg = lane & 3;

    const uint32_t sb = smem_u32(su);

#define ISSUE_TILE(kt, s)                                                           \
    do {                                                                            \
        uint32_t _b = sb + ((uint32_t)(s) * STAGEU) * 4u;                           \
        _Pragma("unroll")                                                           \
        for (int _j = 0; _j < 4; _j++) {                                            \
            int _seg = tid + _j * 512;        /* 0..2047 */                         \
            int _row = _seg >> 3;             /* 0..255 */                          \
            int _ch  = _seg & 7;                                                    \
            cp16(_b + (uint32_t)(_row * P40 * 4 + _ch * 16),                        \
                 (const char*)(X + (size_t)(m0 + _row) * DMODEL + (kt) * BK2) + _ch * 16); \
        }                                                                           \
        _Pragma("unroll")                                                           \
        for (int _j = 0; _j < 2; _j++) {                                            \
            int _seg = tid + _j * 512;        /* 0..1023 */                         \
            int _row = _seg >> 3;             /* 0..127 */                          \
            int _ch  = _seg & 7;                                                    \
            cp16(_b + (uint32_t)(A_STAGEU * 4) + (uint32_t)(_row * P40 * 4 + _ch * 16), \
                 (const char*)(W + (size_t)(n0 + _row) * DMODEL + (kt) * BK2) + _ch * 16); \
        }                                                                           \
    } while (0)

    const int NT = DMODEL / BK2;              // 32
    ISSUE_TILE(0, 0); CP_COMMIT();
    ISSUE_TILE(1, 1); CP_COMMIT();

    for (int kt = 0; kt < NT; kt++) {
        CP_WAIT(1);
        __syncthreads();

        const int s = kt & 1;
        const uint32_t* Asb = su + s * STAGEU;
        const uint32_t* Bsb = Asb + A_STAGEU;

#pragma unroll
        for (int kg = 0; kg < 4; kg++) {
            const int colb = kg * 8 + 2 * tg;
            uint32_t a[4][4], b[4][2];
#pragma unroll
            for (int fm = 0; fm < 4; fm++) {
                const int r = wm * 64 + fm * 16 + g;
                uint2 t0 = *(const uint2*)(Asb + r * P40 + colb);
                uint2 t1 = *(const uint2*)(Asb + (r + 8) * P40 + colb);
                a[fm][0] = t0.x; a[fm][2] = t0.y;
                a[fm][1] = t1.x; a[fm][3] = t1.y;
            }
#pragma unroll
            for (int fn = 0; fn < 4; fn++) {
                const int r = wn * 32 + fn * 8 + g;
                uint2 t = *(const uint2*)(Bsb + r * P40 + colb);
                b[fn][0] = t.x; b[fn][1] = t.y;
            }
#pragma unroll
            for (int fm = 0; fm < 4; fm++)
#pragma unroll
                for (int fn = 0; fn < 4; fn++)
                    mma_tf32(acc[fm][fn], a[fm], b[fn]);
        }

        __syncthreads();
        if (kt + 2 < NT) ISSUE_TILE(kt + 2, s);
        CP_COMMIT();
    }
#undef ISSUE_TILE
}

// ---------------- QKV projection -> pre-split fp16 hi/lo -----------------------
#define QSCALE 0.180336880f

__global__ __launch_bounds__(512, 1) void qkv_tf32_kernel(
    const float* __restrict__ bq, const float* __restrict__ bk, const float* __restrict__ bv)
{
    const int z = blockIdx.z;
    const uint32_t* X = g_Xt + (size_t)z * MTOT * DMODEL;
    const uint32_t* W = g_Wt + (size_t)z * DMODEL * DMODEL;
    const float* Bb   = (z == 0) ? bq : (z == 1) ? bk : bv;
    __half* Hh        = (z == 0) ? g_Qh : (z == 1) ? g_Kh : g_Vh;
    __half* Hl        = (z == 0) ? g_Ql : (z == 1) ? g_Kl : g_Vl;
    const float scale = (z == 0) ? QSCALE : 1.0f;

    const int m0 = blockIdx.y * 256, n0 = blockIdx.x * 128;
    float acc[4][4][4];
#pragma unroll
    for (int i = 0; i < 4; i++)
#pragma unroll
        for (int j = 0; j < 4; j++)
#pragma unroll
            for (int t = 0; t < 4; t++) acc[i][j][t] = 0.f;

    gemm_tf32_main(X, W, m0, n0, acc);

    const int tid  = threadIdx.x;
    const int lane = tid & 31, warp = tid >> 5;
    const int wm = warp >> 2, wn = warp & 3;
    const int g  = lane >> 2, tg = lane & 3;

#pragma unroll
    for (int fn = 0; fn < 4; fn++) {
        const int n  = n0 + wn * 32 + fn * 8 + 2 * tg;
        const int hh = n >> 6, dd = n & 63;
        int ddw;
        if (z < 2) {
            int kk  = dd >> 1;
            int grp = kk >> 3, pig = kk & 7;
            int pp  = ((pig & 3) << 1) | (pig >> 2);
            ddw = (grp * 8 + pp) * 2;
        } else {
            ddw = dd;
        }
        const float b0 = Bb[n], b1 = Bb[n + 1];
#pragma unroll
        for (int fm = 0; fm < 4; fm++) {
#pragma unroll
            for (int half_ = 0; half_ < 2; half_++) {
                const int m  = m0 + wm * 64 + fm * 16 + g + half_ * 8;
                const int bb = m >> 11;
                const int ss = m & (SLEN - 1);
                float v0 = (acc[fm][fn][half_ * 2 + 0] + b0) * scale;
                float v1 = (acc[fm][fn][half_ * 2 + 1] + b1) * scale;
                half2 hi = __floats2half2_rn(v0, v1);
                half2 lo = __floats2half2_rn(v0 - __low2float(hi), v1 - __high2float(hi));
                size_t idx = (((size_t)bb * NHEAD + hh) * SLEN + ss) * DKH + ddw;
                *(half2*)(Hh + idx) = hi;
                *(half2*)(Hl + idx) = lo;
            }
        }
    }
}

// ---------------- output projection -------------------------------------------
__global__ __launch_bounds__(512, 1) void outproj_tf32_kernel(
    const float* __restrict__ Bb, float* __restrict__ Out)
{
    const uint32_t* W = g_Wt + (size_t)3 * DMODEL * DMODEL;
    const int m0 = blockIdx.y * 256, n0 = blockIdx.x * 128;
    float acc[4][4][4];
#pragma unroll
    for (int i = 0; i < 4; i++)
#pragma unroll
        for (int j = 0; j < 4; j++)
#pragma unroll
            for (int t = 0; t < 4; t++) acc[i][j][t] = 0.f;

    gemm_tf32_main(g_AOt, W, m0, n0, acc);

    const int tid  = threadIdx.x;
    const int lane = tid & 31, warp = tid >> 5;
    const int wm = warp >> 2, wn = warp & 3;
    const int g  = lane >> 2, tg = lane & 3;

#pragma unroll
    for (int fn = 0; fn < 4; fn++) {
        const int n = n0 + wn * 32 + fn * 8 + 2 * tg;
        const float b0 = Bb[n], b1 = Bb[n + 1];
#pragma unroll
        for (int fm = 0; fm < 4; fm++) {
#pragma unroll
            for (int half_ = 0; half_ < 2; half_++) {
                const int m = m0 + wm * 64 + fm * 16 + g + half_ * 8;
                *(float2*)(Out + (size_t)m * DMODEL + n) =
                    make_float2(acc[fm][fn][half_ * 2 + 0] + b0,
                                acc[fm][fn][half_ * 2 + 1] + b1);
            }
        }
    }
}

// ============ Flash attention: split-fp16 HMMA, Q+P in registers ===============
#define KPITCH 40
#define VPITCH 36
#define ST_KHI 0
#define ST_KLO 2560
#define ST_VHI 5120
#define ST_VLO 7424
#define STAGE_U 9728
#define ATTN_SMEM_BYTES (2 * STAGE_U * 4)     // 77824

__device__ __forceinline__ uint32_t h2u(half2 h) {
    return *reinterpret_cast<uint32_t*>(&h);
}

__device__ __forceinline__ void split_pack(float x, float y, uint32_t& hi, uint32_t& lo) {
    half2 h = __floats2half2_rn(x, y);
    float lx = x - __low2float(h);
    float ly = y - __high2float(h);
    half2 l = __floats2half2_rn(lx, ly);
    hi = h2u(h);
    lo = h2u(l);
}

__device__ __forceinline__ void mma_f16(float c[4], const uint32_t a[4],
                                        uint32_t b0, uint32_t b1) {
    asm volatile(
        "mma.sync.aligned.m16n8k16.row.col.f32.f16.f16.f32 "
        "{%0,%1,%2,%3}, {%4,%5,%6,%7}, {%8,%9}, {%0,%1,%2,%3};"
        : "+f"(c[0]), "+f"(c[1]), "+f"(c[2]), "+f"(c[3])
        : "r"(a[0]), "r"(a[1]), "r"(a[2]), "r"(a[3]), "r"(b0), "r"(b1));
}

__global__ __launch_bounds__(256, 2) void attn_hmma_kernel() {
    extern __shared__ uint32_t smu[];

    const int qb = 15 - blockIdx.x;            // long CTAs first
    const int bh = blockIdx.y;
    const size_t base = (size_t)bh * SLEN * DKH;
    const __half* Khg = g_Kh + base;
    const __half* Klg = g_Kl + base;
    const __half* Vhg = g_Vh + base;
    const __half* Vlg = g_Vl + base;

    const int tid  = threadIdx.x;
    const int lane = tid & 31, warp = tid >> 5;
    const int g  = lane >> 2, tg = lane & 3;
    const int row0 = warp * 16;
    const uint32_t sb = smem_u32(smu);

#define ATTN_ISSUE(kb_, s_)                                                         \
    do {                                                                            \
        _Pragma("unroll")                                                           \
        for (int _j = 0; _j < 4; _j++) {                                            \
            int _t = tid + _j * 256;                                                \
            int _row = _t >> 4;                                                     \
            int _ch = _t & 15;                                                      \
            int _c7 = _ch & 7;                                                      \
            const __half* _ks = ((_ch < 8) ? Khg : Klg)                             \
                                + (size_t)((kb_) * 64 + _row) * DKH + _c7 * 8;      \
            cp16(sb + (uint32_t)((s_) * STAGE_U + ((_ch < 8) ? ST_KHI : ST_KLO)     \
                                  + _row * KPITCH + _c7 * 4) * 4, _ks);             \
            const __half* _vs = ((_ch < 8) ? Vhg : Vlg)                             \
                                + (size_t)((kb_) * 64 + _row) * DKH + _c7 * 8;      \
            cp16(sb + (uint32_t)((s_) * STAGE_U + ((_ch < 8) ? ST_VHI : ST_VLO)     \
                                  + _row * VPITCH + _c7 * 4) * 4, _vs);             \
        }                                                                           \
    } while (0)

    ATTN_ISSUE(0, 0); CP_COMMIT();
    ATTN_ISSUE(1, 1); CP_COMMIT();

    // ---- Q fragments -> registers (pair-permuted global, LDG.64) ----
    uint32_t qh[4][4], ql[4][4];
    {
        const uint32_t* Qg  = (const uint32_t*)g_Qh + (base >> 1)
                              + (size_t)(qb * 128 + row0 + g) * 32;
        const uint32_t* Qgl = (const uint32_t*)g_Ql + (base >> 1)
                              + (size_t)(qb * 128 + row0 + g) * 32;
#pragma unroll
        for (int ks = 0; ks < 4; ks++) {
            uint2 a0 = *(const uint2*)(Qg + ks * 8 + 2 * tg);
            uint2 a1 = *(const uint2*)(Qg + 8 * 32 + ks * 8 + 2 * tg);
            qh[ks][0] = a0.x; qh[ks][1] = a1.x; qh[ks][2] = a0.y; qh[ks][3] = a1.y;
            uint2 b0 = *(const uint2*)(Qgl + ks * 8 + 2 * tg);
            uint2 b1 = *(const uint2*)(Qgl + 8 * 32 + ks * 8 + 2 * tg);
            ql[ks][0] = b0.x; ql[ks][1] = b1.x; ql[ks][2] = b0.y; ql[ks][3] = b1.y;
        }
    }

    float acc_o[8][4];
#pragma unroll
    for (int j = 0; j < 8; j++)
#pragma unroll
        for (int t = 0; t < 4; t++) acc_o[j][t] = 0.f;
    float m_run[2] = {-1.0e30f, -1.0e30f};
    float l_run[2] = {0.f, 0.f};

    const int ntiles = 2 * (qb + 1);
    for (int kb = 0; kb < ntiles; kb++) {
        CP_WAIT(1);
        __syncthreads();

        const int s = kb & 1;
        const uint32_t* Khi_s = smu + s * STAGE_U + ST_KHI;
        const uint32_t* Klo_s = smu + s * STAGE_U + ST_KLO;
        const uint32_t vhiB = sb + (uint32_t)(s * STAGE_U + ST_VHI) * 4;
        const uint32_t vloB = sb + (uint32_t)(s * STAGE_U + ST_VLO) * 4;

        const bool active = (kb * 64 <= qb * 128 + row0 + 15);

        if (active) {
            float s_acc[8][4];
#pragma unroll
            for (int j = 0; j < 8; j++)
#pragma unroll
                for (int t = 0; t < 4; t++) s_acc[j][t] = 0.f;

#pragma unroll
            for (int ks = 0; ks < 4; ks++) {
#pragma unroll
                for (int fn = 0; fn < 8; fn++) {
                    const int o = (fn * 8 + g) * KPITCH + ks * 8 + 2 * tg;
                    uint2 bh = *(const uint2*)(Khi_s + o);
                    uint2 bl = *(const uint2*)(Klo_s + o);
                    mma_f16(s_acc[fn], qh[ks], bh.x, bh.y);
                    mma_f16(s_acc[fn], qh[ks], bl.x, bl.y);
                    mma_f16(s_acc[fn], ql[ks], bh.x, bh.y);
                }
            }

            uint32_t php[8][2], plp[8][2];
            const bool diag = (kb >= 2 * qb);
#pragma unroll
            for (int h = 0; h < 2; h++) {
                if (diag) {
                    int row = qb * 128 + row0 + g + 8 * h;
#pragma unroll
                    for (int fn = 0; fn < 8; fn++) {
                        int col = kb * 64 + fn * 8 + 2 * tg;
                        if (col > row)     s_acc[fn][h * 2 + 0] = -1.0e30f;
                        if (col + 1 > row) s_acc[fn][h * 2 + 1] = -1.0e30f;
                    }
                }
                float mx = s_acc[0][h * 2];
#pragma unroll
                for (int fn = 0; fn < 8; fn++) {
                    mx = fmaxf(mx, s_acc[fn][h * 2 + 0]);
                    mx = fmaxf(mx, s_acc[fn][h * 2 + 1]);
                }
                mx = fmaxf(mx, __shfl_xor_sync(0xffffffffu, mx, 1));
                mx = fmaxf(mx, __shfl_xor_sync(0xffffffffu, mx, 2));
                float mn   = fmaxf(m_run[h], mx);
                float corr = exp2f(m_run[h] - mn);
                float rs = 0.f;
#pragma unroll
                for (int fn = 0; fn < 8; fn++) {
                    float p0 = exp2f(s_acc[fn][h * 2 + 0] - mn);
                    float p1 = exp2f(s_acc[fn][h * 2 + 1] - mn);
                    rs += p0 + p1;
                    split_pack(p0, p1, php[fn][h], plp[fn][h]);
                }
                rs += __shfl_xor_sync(0xffffffffu, rs, 1);
                rs += __shfl_xor_sync(0xffffffffu, rs, 2);
                l_run[h] = l_run[h] * corr + rs;
                m_run[h] = mn;
#pragma unroll
                for (int fn = 0; fn < 8; fn++) {
                    acc_o[fn][h * 2 + 0] *= corr;
                    acc_o[fn][h * 2 + 1] *= corr;
                }
            }

#pragma unroll
            for (int ks = 0; ks < 4; ks++) {
                uint32_t ahi[4] = { php[2 * ks][0], php[2 * ks][1],
                                    php[2 * ks + 1][0], php[2 * ks + 1][1] };
                uint32_t alo[4] = { plp[2 * ks][0], plp[2 * ks][1],
                                    plp[2 * ks + 1][0], plp[2 * ks + 1][1] };
                const int vrow = ks * 16 + (lane & 15);
                const uint32_t abH = vhiB + (uint32_t)(vrow * VPITCH) * 4;
                const uint32_t abL = vloB + (uint32_t)(vrow * VPITCH) * 4;
#pragma unroll
                for (int fn = 0; fn < 8; fn++) {
                    uint2 bh = ldsm_x2_trans(abH + fn * 16);
                    uint2 bl = ldsm_x2_trans(abL + fn * 16);
                    mma_f16(acc_o[fn], ahi, bh.x, bh.y);
                    mma_f16(acc_o[fn], ahi, bl.x, bl.y);
                    mma_f16(acc_o[fn], alo, bh.x, bh.y);
                }
            }
        }

        __syncthreads();
        if (kb + 2 < ntiles) ATTN_ISSUE(kb + 2, s);
        CP_COMMIT();
    }
#undef ATTN_ISSUE

    // ---- normalize + write tf32 pair-permuted AO directly ----
    const int bb = bh >> 4, hh = bh & 15;
    const int kk0 = 2 * tg, kk1 = 2 * tg + 1;
    const int p0 = ((kk0 & 3) << 1) | (kk0 >> 2);
    const int p1 = ((kk1 & 3) << 1) | (kk1 >> 2);
#pragma unroll
    for (int h = 0; h < 2; h++) {
        float invl = 1.0f / l_run[h];
        int row = qb * 128 + row0 + g + 8 * h;
        uint32_t* dst = g_AOt + ((size_t)bb * SLEN + row) * DMODEL + hh * DKH;
#pragma unroll
        for (int fn = 0; fn < 8; fn++) {
            dst[fn * 8 + p0] = f2tf32(acc_o[fn][h * 2 + 0] * invl);
            dst[fn * 8 + p1] = f2tf32(acc_o[fn][h * 2 + 1] * invl);
        }
    }
}

// ---------------- launch -------------------------------------------------------
extern "C" void kernel_launch(void* const* d_in, const int* in_sizes, int n_in,
                              void* d_out, int out_size) {
    const float* q  = (const float*)d_in[0];
    const float* k  = (const float*)d_in[1];
    const float* v  = (const float*)d_in[2];
    // d_in[3] = mask (int32 tril) — causal, applied analytically
    const float* wq = (const float*)d_in[4];
    const float* bq = (const float*)d_in[5];
    const float* wk = (const float*)d_in[6];
    const float* bk = (const float*)d_in[7];
    const float* wv = (const float*)d_in[8];
    const float* bv = (const float*)d_in[9];
    const float* wo = (const float*)d_in[10];
    const float* bo = (const float*)d_in[11];
    float* out = (float*)d_out;

    cudaFuncSetAttribute(qkv_tf32_kernel, cudaFuncAttributeMaxDynamicSharedMemorySize, GEMM_SMEM);
    cudaFuncSetAttribute(outproj_tf32_kernel, cudaFuncAttributeMaxDynamicSharedMemorySize, GEMM_SMEM);
    cudaFuncSetAttribute(attn_hmma_kernel, cudaFuncAttributeMaxDynamicSharedMemorySize, ATTN_SMEM_BYTES);

    conv_all_kernel<<<14336, 256>>>(q, k, v, wq, wk, wv, wo);

    qkv_tf32_kernel<<<dim3(DMODEL / 128, MTOT / 256, 3), 512, GEMM_SMEM>>>(bq, bk, bv);

    attn_hmma_kernel<<<dim3(SLEN / 128, NB * NHEAD), 256, ATTN_SMEM_BYTES>>>();

    outproj_tf32_kernel<<<dim3(DMODEL / 128, MTOT / 256), 512, GEMM_SMEM>>>(bo, out);
}

// round 11
// speedup vs baseline: 1.6140x; 1.6140x over previous
#include <cuda_runtime.h>
#include <cuda_fp16.h>
#include <cstdint>

#define SLEN    2048
#define DMODEL  1024
#define NHEAD   16
#define DKH     64
#define NB      4
#define MTOT    (NB * SLEN)     // 8192

// ---------------- scratch (allocation-free: __device__ globals) ----------------
// pre-split fp16 hi/lo Q/K/V, layout [B,H,S,64].
// Q is pre-scaled by 0.125*log2(e); Q and K are d-PAIR-PERMUTED; V is natural.
__device__ __half g_Qh[(size_t)NB * NHEAD * SLEN * DKH];
__device__ __half g_Ql[(size_t)NB * NHEAD * SLEN * DKH];
__device__ __half g_Kh[(size_t)NB * NHEAD * SLEN * DKH];
__device__ __half g_Kl[(size_t)NB * NHEAD * SLEN * DKH];
__device__ __half g_Vh[(size_t)NB * NHEAD * SLEN * DKH];
__device__ __half g_Vl[(size_t)NB * NHEAD * SLEN * DKH];

// pre-converted tf32 operands, pair-permuted within each 8-k group
__device__ uint32_t g_Xt[(size_t)3 * MTOT * DMODEL];     // q,k,v inputs
__device__ uint32_t g_Wt[(size_t)4 * DMODEL * DMODEL];   // wq,wk,wv,wo
__device__ uint32_t g_AOt[(size_t)MTOT * DMODEL];        // attn out, tf32 permuted

// ---------------- helpers ------------------------------------------------------
__device__ __forceinline__ uint32_t f2tf32(float f) {
    uint32_t u;
    asm("cvt.rna.tf32.f32 %0, %1;" : "=r"(u) : "f"(f));
    return u;
}

__device__ __forceinline__ void mma_tf32(float c[4], const uint32_t a[4], const uint32_t b[2]) {
    asm volatile(
        "mma.sync.aligned.m16n8k8.row.col.f32.tf32.tf32.f32 "
        "{%0,%1,%2,%3}, {%4,%5,%6,%7}, {%8,%9}, {%0,%1,%2,%3};"
        : "+f"(c[0]), "+f"(c[1]), "+f"(c[2]), "+f"(c[3])
        : "r"(a[0]), "r"(a[1]), "r"(a[2]), "r"(a[3]), "r"(b[0]), "r"(b[1]));
}

__device__ __forceinline__ uint32_t smem_u32(const void* p) {
    uint32_t a;
    asm("{ .reg .u64 t; cvta.to.shared.u64 t, %1; cvt.u32.u64 %0, t; }" : "=r"(a) : "l"(p));
    return a;
}

__device__ __forceinline__ void cp16(uint32_t dst, const void* src) {
    asm volatile("cp.async.cg.shared.global [%0], [%1], 16;" :: "r"(dst), "l"(src));
}
#define CP_COMMIT() asm volatile("cp.async.commit_group;")
#define CP_WAIT(n)  asm volatile("cp.async.wait_group %0;" :: "n"(n))

__device__ __forceinline__ uint2 ldsm_x2_trans(uint32_t addr) {
    uint2 r;
    asm volatile("ldmatrix.sync.aligned.m8n8.x2.trans.shared.b16 {%0,%1}, [%2];"
                 : "=r"(r.x), "=r"(r.y) : "r"(addr));
    return r;
}

// ---------------- fused tf32 pre-convert (all 7 tensors, one launch) -----------
__global__ __launch_bounds__(256) void conv_all_kernel(
    const float* __restrict__ q, const float* __restrict__ k, const float* __restrict__ v,
    const float* __restrict__ wq, const float* __restrict__ wk,
    const float* __restrict__ wv, const float* __restrict__ wo)
{
    int b = blockIdx.x;
    const float* src;
    uint32_t* dst;
    int i;
    if (b < 12288) {
        int sel = b >> 12;
        src = (sel == 0) ? q : (sel == 1) ? k : v;
        dst = g_Xt + (size_t)sel * MTOT * DMODEL;
        i = (b & 4095) * 256 + threadIdx.x;
    } else {
        int sel = (b - 12288) >> 9;
        src = (sel == 0) ? wq : (sel == 1) ? wk : (sel == 2) ? wv : wo;
        dst = g_Wt + (size_t)(sel) * DMODEL * DMODEL;
        i = ((b - 12288) & 511) * 256 + threadIdx.x;
    }
    const float4* s4 = (const float4*)src;
    uint4* d4 = (uint4*)dst;
    float4 v0 = s4[2 * i];
    float4 v1 = s4[2 * i + 1];
    uint4 o0, o1;
    o0.x = f2tf32(v0.x); o0.y = f2tf32(v1.x);
    o0.z = f2tf32(v0.y); o0.w = f2tf32(v1.y);
    o1.x = f2tf32(v0.z); o1.y = f2tf32(v1.z);
    o1.z = f2tf32(v0.w); o1.w = f2tf32(v1.w);
    d4[2 * i]     = o0;
    d4[2 * i + 1] = o1;
}

// ======================= tf32 tensor-core GEMM (R9 config) =====================
// 128x128 CTA tile, 256 threads (2m x 4n warps, warp tile 64x32), BK=32, 2-stage.
#define BK2 32
#define P40 40
#define STAGEU (128 * P40)                    // u32 per operand per stage
#define GEMM_SMEM (2 * 2 * STAGEU * 4)        // 81920 bytes

__device__ __forceinline__ void gemm_tf32_main(const uint32_t* __restrict__ X,
                                               const uint32_t* __restrict__ W,
                                               int m0, int n0,
                                               float acc[4][4][4]) {
    extern __shared__ uint32_t su[];
    const int tid  = threadIdx.x;
    const int lane = tid & 31, warp = tid >> 5;
    const int wm = warp >> 2, wn = warp & 3;
    const int g  = lane >> 2, tg = lane & 3;

    const uint32_t sb = smem_u32(su);

#define ISSUE_TILE(kt, s)                                                           \
    do {                                                                            \
        uint32_t _b = sb + ((uint32_t)(s) * 2 * STAGEU) * 4u;                       \
        _Pragma("unroll")                                                           \
        for (int _j = 0; _j < 4; _j++) {                                            \
            int _seg = tid + _j * 256;                                              \
            int _row = _seg >> 3;                                                   \
            int _ch  = _seg & 7;                                                    \
            uint32_t _off = (uint32_t)(_row * P40 * 4 + _ch * 16);                  \
            cp16(_b + _off,                                                         \
                 (const char*)(X + (size_t)(m0 + _row) * DMODEL + (kt) * BK2) + _ch * 16); \
            cp16(_b + (uint32_t)(STAGEU * 4) + _off,                                \
                 (const char*)(W + (size_t)(n0 + _row) * DMODEL + (kt) * BK2) + _ch * 16); \
        }                                                                           \
    } while (0)

    const int NT = DMODEL / BK2;              // 32
    ISSUE_TILE(0, 0); CP_COMMIT();
    ISSUE_TILE(1, 1); CP_COMMIT();

    for (int kt = 0; kt < NT; kt++) {
        CP_WAIT(1);
        __syncthreads();

        const int s = kt & 1;
        const uint32_t* Asb = su + s * 2 * STAGEU;
        const uint32_t* Bsb = Asb + STAGEU;

#pragma unroll
        for (int kg = 0; kg < 4; kg++) {
            const int colb = kg * 8 + 2 * tg;
            uint32_t a[4][4], b[4][2];
#pragma unroll
            for (int fm = 0; fm < 4; fm++) {
                const int r = wm * 64 + fm * 16 + g;
                uint2 t0 = *(const uint2*)(Asb + r * P40 + colb);
                uint2 t1 = *(const uint2*)(Asb + (r + 8) * P40 + colb);
                a[fm][0] = t0.x; a[fm][2] = t0.y;
                a[fm][1] = t1.x; a[fm][3] = t1.y;
            }
#pragma unroll
            for (int fn = 0; fn < 4; fn++) {
                const int r = wn * 32 + fn * 8 + g;
                uint2 t = *(const uint2*)(Bsb + r * P40 + colb);
                b[fn][0] = t.x; b[fn][1] = t.y;
            }
#pragma unroll
            for (int fm = 0; fm < 4; fm++)
#pragma unroll
                for (int fn = 0; fn < 4; fn++)
                    mma_tf32(acc[fm][fn], a[fm], b[fn]);
        }

        __syncthreads();
        if (kt + 2 < NT) ISSUE_TILE(kt + 2, s);
        CP_COMMIT();
    }
#undef ISSUE_TILE
}

// ---------------- QKV projection -> pre-split fp16 hi/lo -----------------------
#define QSCALE 0.180336880f

__global__ __launch_bounds__(256, 2) void qkv_tf32_kernel(
    const float* __restrict__ bq, const float* __restrict__ bk, const float* __restrict__ bv)
{
    const int z = blockIdx.z;
    const uint32_t* X = g_Xt + (size_t)z * MTOT * DMODEL;
    const uint32_t* W = g_Wt + (size_t)z * DMODEL * DMODEL;
    const float* Bb   = (z == 0) ? bq : (z == 1) ? bk : bv;
    __half* Hh        = (z == 0) ? g_Qh : (z == 1) ? g_Kh : g_Vh;
    __half* Hl        = (z == 0) ? g_Ql : (z == 1) ? g_Kl : g_Vl;
    const float scale = (z == 0) ? QSCALE : 1.0f;

    const int m0 = blockIdx.y * 128, n0 = blockIdx.x * 128;
    float acc[4][4][4];
#pragma unroll
    for (int i = 0; i < 4; i++)
#pragma unroll
        for (int j = 0; j < 4; j++)
#pragma unroll
            for (int t = 0; t < 4; t++) acc[i][j][t] = 0.f;

    gemm_tf32_main(X, W, m0, n0, acc);

    const int tid  = threadIdx.x;
    const int lane = tid & 31, warp = tid >> 5;
    const int wm = warp >> 2, wn = warp & 3;
    const int g  = lane >> 2, tg = lane & 3;

#pragma unroll
    for (int fn = 0; fn < 4; fn++) {
        const int n  = n0 + wn * 32 + fn * 8 + 2 * tg;
        const int hh = n >> 6, dd = n & 63;
        int ddw;
        if (z < 2) {
            int kk  = dd >> 1;
            int grp = kk >> 3, pig = kk & 7;
            int pp  = ((pig & 3) << 1) | (pig >> 2);
            ddw = (grp * 8 + pp) * 2;
        } else {
            ddw = dd;
        }
        const float b0 = Bb[n], b1 = Bb[n + 1];
#pragma unroll
        for (int fm = 0; fm < 4; fm++) {
#pragma unroll
            for (int half_ = 0; half_ < 2; half_++) {
                const int m  = m0 + wm * 64 + fm * 16 + g + half_ * 8;
                const int bb = m >> 11;
                const int ss = m & (SLEN - 1);
                float v0 = (acc[fm][fn][half_ * 2 + 0] + b0) * scale;
                float v1 = (acc[fm][fn][half_ * 2 + 1] + b1) * scale;
                half2 hi = __floats2half2_rn(v0, v1);
                half2 lo = __floats2half2_rn(v0 - __low2float(hi), v1 - __high2float(hi));
                size_t idx = (((size_t)bb * NHEAD + hh) * SLEN + ss) * DKH + ddw;
                *(half2*)(Hh + idx) = hi;
                *(half2*)(Hl + idx) = lo;
            }
        }
    }
}

// ---------------- output projection -------------------------------------------
__global__ __launch_bounds__(256, 2) void outproj_tf32_kernel(
    const float* __restrict__ Bb, float* __restrict__ Out)
{
    const uint32_t* W = g_Wt + (size_t)3 * DMODEL * DMODEL;
    const int m0 = blockIdx.y * 128, n0 = blockIdx.x * 128;
    float acc[4][4][4];
#pragma unroll
    for (int i = 0; i < 4; i++)
#pragma unroll
        for (int j = 0; j < 4; j++)
#pragma unroll
            for (int t = 0; t < 4; t++) acc[i][j][t] = 0.f;

    gemm_tf32_main(g_AOt, W, m0, n0, acc);

    const int tid  = threadIdx.x;
    const int lane = tid & 31, warp = tid >> 5;
    const int wm = warp >> 2, wn = warp & 3;
    const int g  = lane >> 2, tg = lane & 3;

#pragma unroll
    for (int fn = 0; fn < 4; fn++) {
        const int n = n0 + wn * 32 + fn * 8 + 2 * tg;
        const float b0 = Bb[n], b1 = Bb[n + 1];
#pragma unroll
        for (int fm = 0; fm < 4; fm++) {
#pragma unroll
            for (int half_ = 0; half_ < 2; half_++) {
                const int m = m0 + wm * 64 + fm * 16 + g + half_ * 8;
                *(float2*)(Out + (size_t)m * DMODEL + n) =
                    make_float2(acc[fm][fn][half_ * 2 + 0] + b0,
                                acc[fm][fn][half_ * 2 + 1] + b1);
            }
        }
    }
}

// ============ Flash attention: 256-row Q tiles, 3-stage single-sync ============
// 512 threads, 16 warps x 16 rows. smem: 3 stages of
// { K hi/lo [64][40], V hi/lo [64][36] } (u32 units).
#define KPITCH 40
#define VPITCH 36
#define ST_KHI 0
#define ST_KLO 2560
#define ST_VHI 5120
#define ST_VLO 7424
#define STAGE_U 9728
#define ATTN_SMEM_BYTES (3 * STAGE_U * 4)     // 116736

__device__ __forceinline__ uint32_t h2u(half2 h) {
    return *reinterpret_cast<uint32_t*>(&h);
}

__device__ __forceinline__ void split_pack(float x, float y, uint32_t& hi, uint32_t& lo) {
    half2 h = __floats2half2_rn(x, y);
    float lx = x - __low2float(h);
    float ly = y - __high2float(h);
    half2 l = __floats2half2_rn(lx, ly);
    hi = h2u(h);
    lo = h2u(l);
}

__device__ __forceinline__ void mma_f16(float c[4], const uint32_t a[4],
                                        uint32_t b0, uint32_t b1) {
    asm volatile(
        "mma.sync.aligned.m16n8k16.row.col.f32.f16.f16.f32 "
        "{%0,%1,%2,%3}, {%4,%5,%6,%7}, {%8,%9}, {%0,%1,%2,%3};"
        : "+f"(c[0]), "+f"(c[1]), "+f"(c[2]), "+f"(c[3])
        : "r"(a[0]), "r"(a[1]), "r"(a[2]), "r"(a[3]), "r"(b0), "r"(b1));
}

__global__ __launch_bounds__(512, 1) void attn_hmma_kernel() {
    extern __shared__ uint32_t smu[];

    const int qb = 7 - blockIdx.x;             // long CTAs first; rows qb*256..+255
    const int bh = blockIdx.y;
    const size_t base = (size_t)bh * SLEN * DKH;
    const __half* Khg = g_Kh + base;
    const __half* Klg = g_Kl + base;
    const __half* Vhg = g_Vh + base;
    const __half* Vlg = g_Vl + base;

    const int tid  = threadIdx.x;
    const int lane = tid & 31, warp = tid >> 5;
    const int g  = lane >> 2, tg = lane & 3;
    const int row0 = warp * 16;                // local rows row0..row0+15 of 256
    const uint32_t sb = smem_u32(smu);

#define ATTN_ISSUE(kb_, s_)                                                         \
    do {                                                                            \
        _Pragma("unroll")                                                           \
        for (int _j = 0; _j < 2; _j++) {                                            \
            int _t = tid + _j * 512;          /* 0..1023 */                         \
            int _row = _t >> 4;               /* 0..63  */                          \
            int _ch = _t & 15;                                                      \
            int _c7 = _ch & 7;                                                      \
            const __half* _ks = ((_ch < 8) ? Khg : Klg)                             \
                                + (size_t)((kb_) * 64 + _row) * DKH + _c7 * 8;      \
            cp16(sb + (uint32_t)((s_) * STAGE_U + ((_ch < 8) ? ST_KHI : ST_KLO)     \
                                  + _row * KPITCH + _c7 * 4) * 4, _ks);             \
            const __half* _vs = ((_ch < 8) ? Vhg : Vlg)                             \
                                + (size_t)((kb_) * 64 + _row) * DKH + _c7 * 8;      \
            cp16(sb + (uint32_t)((s_) * STAGE_U + ((_ch < 8) ? ST_VHI : ST_VLO)     \
                                  + _row * VPITCH + _c7 * 4) * 4, _vs);             \
        }                                                                           \
    } while (0)

    ATTN_ISSUE(0, 0); CP_COMMIT();
    ATTN_ISSUE(1, 1); CP_COMMIT();

    // ---- Q fragments -> registers (pair-permuted global, LDG.64) ----
    uint32_t qh[4][4], ql[4][4];
    {
        const uint32_t* Qg  = (const uint32_t*)g_Qh + (base >> 1)
                              + (size_t)(qb * 256 + row0 + g) * 32;
        const uint32_t* Qgl = (const uint32_t*)g_Ql + (base >> 1)
                              + (size_t)(qb * 256 + row0 + g) * 32;
#pragma unroll
        for (int ks = 0; ks < 4; ks++) {
            uint2 a0 = *(const uint2*)(Qg + ks * 8 + 2 * tg);
            uint2 a1 = *(const uint2*)(Qg + 8 * 32 + ks * 8 + 2 * tg);
            qh[ks][0] = a0.x; qh[ks][1] = a1.x; qh[ks][2] = a0.y; qh[ks][3] = a1.y;
            uint2 b0 = *(const uint2*)(Qgl + ks * 8 + 2 * tg);
            uint2 b1 = *(const uint2*)(Qgl + 8 * 32 + ks * 8 + 2 * tg);
            ql[ks][0] = b0.x; ql[ks][1] = b1.x; ql[ks][2] = b0.y; ql[ks][3] = b1.y;
        }
    }

    float acc_o[8][4];
#pragma unroll
    for (int j = 0; j < 8; j++)
#pragma unroll
        for (int t = 0; t < 4; t++) acc_o[j][t] = 0.f;
    float m_run[2] = {-1.0e30f, -1.0e30f};
    float l_run[2] = {0.f, 0.f};

    const int ntiles = 4 * (qb + 1);
    for (int kb = 0; kb < ntiles; kb++) {
        // single-sync 3-stage: wait for tile kb, sync (covers last reads of the
        // stage about to be refilled, done in iteration kb-1), then prefetch kb+2.
        CP_WAIT(1);
        __syncthreads();
        if (kb + 2 < ntiles) ATTN_ISSUE(kb + 2, (kb + 2) % 3);
        CP_COMMIT();

        const int s = kb % 3;
        const uint32_t* Khi_s = smu + s * STAGE_U + ST_KHI;
        const uint32_t* Klo_s = smu + s * STAGE_U + ST_KLO;
        const uint32_t vhiB = sb + (uint32_t)(s * STAGE_U + ST_VHI) * 4;
        const uint32_t vloB = sb + (uint32_t)(s * STAGE_U + ST_VLO) * 4;

        const bool active = (kb * 64 <= qb * 256 + row0 + 15);

        if (active) {
            // ---- S = Q K^T (3-term split), 16 rows x 64 cols ----
            float s_acc[8][4];
#pragma unroll
            for (int j = 0; j < 8; j++)
#pragma unroll
                for (int t = 0; t < 4; t++) s_acc[j][t] = 0.f;

#pragma unroll
            for (int ks = 0; ks < 4; ks++) {
#pragma unroll
                for (int fn = 0; fn < 8; fn++) {
                    const int o = (fn * 8 + g) * KPITCH + ks * 8 + 2 * tg;
                    uint2 bh = *(const uint2*)(Khi_s + o);
                    uint2 bl = *(const uint2*)(Klo_s + o);
                    mma_f16(s_acc[fn], qh[ks], bh.x, bh.y);
                    mma_f16(s_acc[fn], qh[ks], bl.x, bl.y);
                    mma_f16(s_acc[fn], ql[ks], bh.x, bh.y);
                }
            }

            // ---- mask + online softmax (base-2) + pack P into registers ----
            uint32_t php[8][2], plp[8][2];
            const bool diag = (kb >= 4 * qb);
#pragma unroll
            for (int h = 0; h < 2; h++) {
                if (diag) {
                    int row = qb * 256 + row0 + g + 8 * h;
#pragma unroll
                    for (int fn = 0; fn < 8; fn++) {
                        int col = kb * 64 + fn * 8 + 2 * tg;
                        if (col > row)     s_acc[fn][h * 2 + 0] = -1.0e30f;
                        if (col + 1 > row) s_acc[fn][h * 2 + 1] = -1.0e30f;
                    }
                }
                float mx = s_acc[0][h * 2];
#pragma unroll
                for (int fn = 0; fn < 8; fn++) {
                    mx = fmaxf(mx, s_acc[fn][h * 2 + 0]);
                    mx = fmaxf(mx, s_acc[fn][h * 2 + 1]);
                }
                mx = fmaxf(mx, __shfl_xor_sync(0xffffffffu, mx, 1));
                mx = fmaxf(mx, __shfl_xor_sync(0xffffffffu, mx, 2));
                float mn   = fmaxf(m_run[h], mx);
                float corr = exp2f(m_run[h] - mn);
                float rs = 0.f;
#pragma unroll
                for (int fn = 0; fn < 8; fn++) {
                    float p0 = exp2f(s_acc[fn][h * 2 + 0] - mn);
                    float p1 = exp2f(s_acc[fn][h * 2 + 1] - mn);
                    rs += p0 + p1;
                    split_pack(p0, p1, php[fn][h], plp[fn][h]);
                }
                rs += __shfl_xor_sync(0xffffffffu, rs, 1);
                rs += __shfl_xor_sync(0xffffffffu, rs, 2);
                l_run[h] = l_run[h] * corr + rs;
                m_run[h] = mn;
#pragma unroll
                for (int fn = 0; fn < 8; fn++) {
                    acc_o[fn][h * 2 + 0] *= corr;
                    acc_o[fn][h * 2 + 1] *= corr;
                }
            }

            // ---- O += P V (P fragments are thread-local registers) ----
#pragma unroll
            for (int ks = 0; ks < 4; ks++) {
                uint32_t ahi[4] = { php[2 * ks][0], php[2 * ks][1],
                                    php[2 * ks + 1][0], php[2 * ks + 1][1] };
                uint32_t alo[4] = { plp[2 * ks][0], plp[2 * ks][1],
                                    plp[2 * ks + 1][0], plp[2 * ks + 1][1] };
                const int vrow = ks * 16 + (lane & 15);
                const uint32_t abH = vhiB + (uint32_t)(vrow * VPITCH) * 4;
                const uint32_t abL = vloB + (uint32_t)(vrow * VPITCH) * 4;
#pragma unroll
                for (int fn = 0; fn < 8; fn++) {
                    uint2 bh = ldsm_x2_trans(abH + fn * 16);
                    uint2 bl = ldsm_x2_trans(abL + fn * 16);
                    mma_f16(acc_o[fn], ahi, bh.x, bh.y);
                    mma_f16(acc_o[fn], ahi, bl.x, bl.y);
                    mma_f16(acc_o[fn], alo, bh.x, bh.y);
                }
            }
        }
    }
#undef ATTN_ISSUE

    // ---- normalize + write tf32 pair-permuted AO directly ----
    const int bb = bh >> 4, hh = bh & 15;
    const int kk0 = 2 * tg, kk1 = 2 * tg + 1;
    const int p0 = ((kk0 & 3) << 1) | (kk0 >> 2);
    const int p1 = ((kk1 & 3) << 1) | (kk1 >> 2);
#pragma unroll
    for (int h = 0; h < 2; h++) {
        float invl = 1.0f / l_run[h];
        int row = qb * 256 + row0 + g + 8 * h;
        uint32_t* dst = g_AOt + ((size_t)bb * SLEN + row) * DMODEL + hh * DKH;
#pragma unroll
        for (int fn = 0; fn < 8; fn++) {
            dst[fn * 8 + p0] = f2tf32(acc_o[fn][h * 2 + 0] * invl);
            dst[fn * 8 + p1] = f2tf32(acc_o[fn][h * 2 + 1] * invl);
        }
    }
}

// ---------------- launch -------------------------------------------------------
extern "C" void kernel_launch(void* const* d_in, const int* in_sizes, int n_in,
                              void* d_out, int out_size) {
    const float* q  = (const float*)d_in[0];
    const float* k  = (const float*)d_in[1];
    const float* v  = (const float*)d_in[2];
    // d_in[3] = mask (int32 tril) — causal, applied analytically
    const float* wq = (const float*)d_in[4];
    const float* bq = (const float*)d_in[5];
    const float* wk = (const float*)d_in[6];
    const float* bk = (const float*)d_in[7];
    const float* wv = (const float*)d_in[8];
    const float* bv = (const float*)d_in[9];
    const float* wo = (const float*)d_in[10];
    const float* bo = (const float*)d_in[11];
    float* out = (float*)d_out;

    cudaFuncSetAttribute(qkv_tf32_kernel, cudaFuncAttributeMaxDynamicSharedMemorySize, GEMM_SMEM);
    cudaFuncSetAttribute(outproj_tf32_kernel, cudaFuncAttributeMaxDynamicSharedMemorySize, GEMM_SMEM);
    cudaFuncSetAttribute(attn_hmma_kernel, cudaFuncAttributeMaxDynamicSharedMemorySize, ATTN_SMEM_BYTES);

    conv_all_kernel<<<14336, 256>>>(q, k, v, wq, wk, wv, wo);

    qkv_tf32_kernel<<<dim3(DMODEL / 128, MTOT / 128, 3), 256, GEMM_SMEM>>>(bq, bk, bv);

    attn_hmma_kernel<<<dim3(SLEN / 256, NB * NHEAD), 512, ATTN_SMEM_BYTES>>>();

    outproj_tf32_kernel<<<dim3(DMODEL / 128, MTOT / 128), 256, GEMM_SMEM>>>(bo, out);
}

// round 12
// speedup vs baseline: 1.6685x; 1.0338x over previous
#include <cuda_runtime.h>
#include <cuda_fp16.h>
#include <cstdint>

#define SLEN    2048
#define DMODEL  1024
#define NHEAD   16
#define DKH     64
#define NB      4
#define MTOT    (NB * SLEN)     // 8192

// ---------------- scratch (allocation-free: __device__ globals) ----------------
// pre-split fp16 hi/lo Q/K/V, layout [B,H,S,64].
// Q is pre-scaled by 0.125*log2(e); Q and K are d-PAIR-PERMUTED; V is natural.
__device__ __half g_Qh[(size_t)NB * NHEAD * SLEN * DKH];
__device__ __half g_Ql[(size_t)NB * NHEAD * SLEN * DKH];
__device__ __half g_Kh[(size_t)NB * NHEAD * SLEN * DKH];
__device__ __half g_Kl[(size_t)NB * NHEAD * SLEN * DKH];
__device__ __half g_Vh[(size_t)NB * NHEAD * SLEN * DKH];
__device__ __half g_Vl[(size_t)NB * NHEAD * SLEN * DKH];

// tf32 operands.
// g_Xt / g_AOt (GEMM A-side): per 32-k tile, u32 slot = tg*8 + kg*2 + j holds
//   k_{kg*8 + tg + 4j}  (contiguous 8-u32 group per tg -> uint4 fragment loads)
// g_Wt (GEMM B-side): old pair-permutation per 8-k group [k0,k4,k1,k5,k2,k6,k3,k7]
__device__ uint32_t g_Xt[(size_t)3 * MTOT * DMODEL];     // q,k,v inputs
__device__ uint32_t g_Wt[(size_t)4 * DMODEL * DMODEL];   // wq,wk,wv,wo
__device__ uint32_t g_AOt[(size_t)MTOT * DMODEL];        // attn out

// ---------------- helpers ------------------------------------------------------
__device__ __forceinline__ uint32_t f2tf32(float f) {
    uint32_t u;
    asm("cvt.rna.tf32.f32 %0, %1;" : "=r"(u) : "f"(f));
    return u;
}

__device__ __forceinline__ void mma_tf32(float c[4], const uint32_t a[4], const uint32_t b[2]) {
    asm volatile(
        "mma.sync.aligned.m16n8k8.row.col.f32.tf32.tf32.f32 "
        "{%0,%1,%2,%3}, {%4,%5,%6,%7}, {%8,%9}, {%0,%1,%2,%3};"
        : "+f"(c[0]), "+f"(c[1]), "+f"(c[2]), "+f"(c[3])
        : "r"(a[0]), "r"(a[1]), "r"(a[2]), "r"(a[3]), "r"(b[0]), "r"(b[1]));
}

__device__ __forceinline__ uint32_t smem_u32(const void* p) {
    uint32_t a;
    asm("{ .reg .u64 t; cvta.to.shared.u64 t, %1; cvt.u32.u64 %0, t; }" : "=r"(a) : "l"(p));
    return a;
}

__device__ __forceinline__ void cp16(uint32_t dst, const void* src) {
    asm volatile("cp.async.cg.shared.global [%0], [%1], 16;" :: "r"(dst), "l"(src));
}
#define CP_COMMIT() asm volatile("cp.async.commit_group;")
#define CP_WAIT(n)  asm volatile("cp.async.wait_group %0;" :: "n"(n))

__device__ __forceinline__ uint2 ldsm_x2_trans(uint32_t addr) {
    uint2 r;
    asm volatile("ldmatrix.sync.aligned.m8n8.x2.trans.shared.b16 {%0,%1}, [%2];"
                 : "=r"(r.x), "=r"(r.y) : "r"(addr));
    return r;
}

// ---------------- fused tf32 pre-convert (all 7 tensors, one launch) -----------
__global__ __launch_bounds__(256) void conv_all_kernel(
    const float* __restrict__ q, const float* __restrict__ k, const float* __restrict__ v,
    const float* __restrict__ wq, const float* __restrict__ wk,
    const float* __restrict__ wv, const float* __restrict__ wo)
{
    int b = blockIdx.x;
    if (b < 12288) {
        // X tensors: NEW contiguous-per-tg permutation
        int sel = b >> 12;
        const float* src = (sel == 0) ? q : (sel == 1) ? k : v;
        uint32_t* dst = g_Xt + (size_t)sel * MTOT * DMODEL;
        int i = (b & 4095) * 256 + threadIdx.x;     // 8-float group index
        const float4* s4 = (const float4*)src;
        float4 v0 = s4[2 * i];
        float4 v1 = s4[2 * i + 1];
        int tile = i >> 2, kg = i & 3;
        uint2* d2 = (uint2*)dst + (size_t)tile * 16 + kg;
        d2[0]  = make_uint2(f2tf32(v0.x), f2tf32(v1.x));
        d2[4]  = make_uint2(f2tf32(v0.y), f2tf32(v1.y));
        d2[8]  = make_uint2(f2tf32(v0.z), f2tf32(v1.z));
        d2[12] = make_uint2(f2tf32(v0.w), f2tf32(v1.w));
    } else {
        // W tensors: old pair-permutation
        int sel = (b - 12288) >> 9;
        const float* src = (sel == 0) ? wq : (sel == 1) ? wk : (sel == 2) ? wv : wo;
        uint32_t* dst = g_Wt + (size_t)sel * DMODEL * DMODEL;
        int i = ((b - 12288) & 511) * 256 + threadIdx.x;
        const float4* s4 = (const float4*)src;
        uint4* d4 = (uint4*)dst;
        float4 v0 = s4[2 * i];
        float4 v1 = s4[2 * i + 1];
        uint4 o0, o1;
        o0.x = f2tf32(v0.x); o0.y = f2tf32(v1.x);
        o0.z = f2tf32(v0.y); o0.w = f2tf32(v1.y);
        o1.x = f2tf32(v0.z); o1.y = f2tf32(v1.z);
        o1.z = f2tf32(v0.w); o1.w = f2tf32(v1.w);
        d4[2 * i]     = o0;
        d4[2 * i + 1] = o1;
    }
}

// ======================= tf32 tensor-core GEMM =================================
// 128x128 CTA tile, 256 threads (2m x 4n warps, warp tile 64x32), BK=32, 2-stage.
// A operand: new layout, pitch 44, uint4 fragment loads (conflict-free).
// B operand: old layout, pitch 40, uint2 fragment loads.
#define BK2 32
#define PA44 44
#define PB40 40
#define AS_U (128 * PA44)                     // 5632 u32
#define BS_U (128 * PB40)                     // 5120 u32
#define STG_U (AS_U + BS_U)                   // 10752 u32
#define GEMM_SMEM (2 * STG_U * 4)             // 86016 bytes

__device__ __forceinline__ void gemm_tf32_main(const uint32_t* __restrict__ X,
                                               const uint32_t* __restrict__ W,
                                               int m0, int n0,
                                               float acc[4][4][4]) {
    extern __shared__ uint32_t su[];
    const int tid  = threadIdx.x;
    const int lane = tid & 31, warp = tid >> 5;
    const int wm = warp >> 2, wn = warp & 3;
    const int g  = lane >> 2, tg = lane & 3;

    const uint32_t sb = smem_u32(su);

#define ISSUE_TILE(kt, s)                                                           \
    do {                                                                            \
        uint32_t _b = sb + ((uint32_t)(s) * STG_U) * 4u;                            \
        _Pragma("unroll")                                                           \
        for (int _j = 0; _j < 4; _j++) {                                            \
            int _seg = tid + _j * 256;                                              \
            int _row = _seg >> 3;                                                   \
            int _ch  = _seg & 7;                                                    \
            cp16(_b + (uint32_t)(_row * PA44 * 4 + _ch * 16),                       \
                 (const char*)(X + (size_t)(m0 + _row) * DMODEL + (kt) * BK2) + _ch * 16); \
            cp16(_b + (uint32_t)(AS_U * 4) + (uint32_t)(_row * PB40 * 4 + _ch * 16), \
                 (const char*)(W + (size_t)(n0 + _row) * DMODEL + (kt) * BK2) + _ch * 16); \
        }                                                                           \
    } while (0)

    const int NT = DMODEL / BK2;              // 32
    ISSUE_TILE(0, 0); CP_COMMIT();
    ISSUE_TILE(1, 1); CP_COMMIT();

    for (int kt = 0; kt < NT; kt++) {
        CP_WAIT(1);
        __syncthreads();

        const int s = kt & 1;
        const uint32_t* Asb = su + s * STG_U;
        const uint32_t* Bsb = Asb + AS_U;

#pragma unroll
        for (int kgp = 0; kgp < 2; kgp++) {
            const int colA = tg * 8 + kgp * 4;
            uint4 a0[4], a1[4];
#pragma unroll
            for (int fm = 0; fm < 4; fm++) {
                const int r = wm * 64 + fm * 16 + g;
                a0[fm] = *(const uint4*)(Asb + r * PA44 + colA);
                a1[fm] = *(const uint4*)(Asb + (r + 8) * PA44 + colA);
            }
#pragma unroll
            for (int kh = 0; kh < 2; kh++) {
                const int kg = kgp * 2 + kh;
                const int colB = kg * 8 + 2 * tg;
                uint32_t b[4][2];
#pragma unroll
                for (int fn = 0; fn < 4; fn++) {
                    uint2 t = *(const uint2*)(Bsb + (wn * 32 + fn * 8 + g) * PB40 + colB);
                    b[fn][0] = t.x; b[fn][1] = t.y;
                }
#pragma unroll
                for (int fm = 0; fm < 4; fm++) {
                    uint32_t a[4];
                    if (kh == 0) {
                        a[0] = a0[fm].x; a[1] = a1[fm].x; a[2] = a0[fm].y; a[3] = a1[fm].y;
                    } else {
                        a[0] = a0[fm].z; a[1] = a1[fm].z; a[2] = a0[fm].w; a[3] = a1[fm].w;
                    }
#pragma unroll
                    for (int fn = 0; fn < 4; fn++)
                        mma_tf32(acc[fm][fn], a, b[fn]);
                }
            }
        }

        __syncthreads();
        if (kt + 2 < NT) ISSUE_TILE(kt + 2, s);
        CP_COMMIT();
    }
#undef ISSUE_TILE
}

// ---------------- QKV projection -> pre-split fp16 hi/lo -----------------------
#define QSCALE 0.180336880f

__global__ __launch_bounds__(256, 2) void qkv_tf32_kernel(
    const float* __restrict__ bq, const float* __restrict__ bk, const float* __restrict__ bv)
{
    const int z = blockIdx.z;
    const uint32_t* X = g_Xt + (size_t)z * MTOT * DMODEL;
    const uint32_t* W = g_Wt + (size_t)z * DMODEL * DMODEL;
    const float* Bb   = (z == 0) ? bq : (z == 1) ? bk : bv;
    __half* Hh        = (z == 0) ? g_Qh : (z == 1) ? g_Kh : g_Vh;
    __half* Hl        = (z == 0) ? g_Ql : (z == 1) ? g_Kl : g_Vl;
    const float scale = (z == 0) ? QSCALE : 1.0f;

    const int m0 = blockIdx.y * 128, n0 = blockIdx.x * 128;
    float acc[4][4][4];
#pragma unroll
    for (int i = 0; i < 4; i++)
#pragma unroll
        for (int j = 0; j < 4; j++)
#pragma unroll
            for (int t = 0; t < 4; t++) acc[i][j][t] = 0.f;

    gemm_tf32_main(X, W, m0, n0, acc);

    const int tid  = threadIdx.x;
    const int lane = tid & 31, warp = tid >> 5;
    const int wm = warp >> 2, wn = warp & 3;
    const int g  = lane >> 2, tg = lane & 3;

#pragma unroll
    for (int fn = 0; fn < 4; fn++) {
        const int n  = n0 + wn * 32 + fn * 8 + 2 * tg;
        const int hh = n >> 6, dd = n & 63;
        int ddw;
        if (z < 2) {
            int kk  = dd >> 1;
            int grp = kk >> 3, pig = kk & 7;
            int pp  = ((pig & 3) << 1) | (pig >> 2);
            ddw = (grp * 8 + pp) * 2;
        } else {
            ddw = dd;
        }
        const float b0 = Bb[n], b1 = Bb[n + 1];
#pragma unroll
        for (int fm = 0; fm < 4; fm++) {
#pragma unroll
            for (int half_ = 0; half_ < 2; half_++) {
                const int m  = m0 + wm * 64 + fm * 16 + g + half_ * 8;
                const int bb = m >> 11;
                const int ss = m & (SLEN - 1);
                float v0 = (acc[fm][fn][half_ * 2 + 0] + b0) * scale;
                float v1 = (acc[fm][fn][half_ * 2 + 1] + b1) * scale;
                half2 hi = __floats2half2_rn(v0, v1);
                half2 lo = __floats2half2_rn(v0 - __low2float(hi), v1 - __high2float(hi));
                size_t idx = (((size_t)bb * NHEAD + hh) * SLEN + ss) * DKH + ddw;
                *(half2*)(Hh + idx) = hi;
                *(half2*)(Hl + idx) = lo;
            }
        }
    }
}

// ---------------- output projection -------------------------------------------
__global__ __launch_bounds__(256, 2) void outproj_tf32_kernel(
    const float* __restrict__ Bb, float* __restrict__ Out)
{
    const uint32_t* W = g_Wt + (size_t)3 * DMODEL * DMODEL;
    const int m0 = blockIdx.y * 128, n0 = blockIdx.x * 128;
    float acc[4][4][4];
#pragma unroll
    for (int i = 0; i < 4; i++)
#pragma unroll
        for (int j = 0; j < 4; j++)
#pragma unroll
            for (int t = 0; t < 4; t++) acc[i][j][t] = 0.f;

    gemm_tf32_main(g_AOt, W, m0, n0, acc);

    const int tid  = threadIdx.x;
    const int lane = tid & 31, warp = tid >> 5;
    const int wm = warp >> 2, wn = warp & 3;
    const int g  = lane >> 2, tg = lane & 3;

#pragma unroll
    for (int fn = 0; fn < 4; fn++) {
        const int n = n0 + wn * 32 + fn * 8 + 2 * tg;
        const float b0 = Bb[n], b1 = Bb[n + 1];
#pragma unroll
        for (int fm = 0; fm < 4; fm++) {
#pragma unroll
            for (int half_ = 0; half_ < 2; half_++) {
                const int m = m0 + wm * 64 + fm * 16 + g + half_ * 8;
                *(float2*)(Out + (size_t)m * DMODEL + n) =
                    make_float2(acc[fm][fn][half_ * 2 + 0] + b0,
                                acc[fm][fn][half_ * 2 + 1] + b1);
            }
        }
    }
}

// ============ Flash attention (R9 shape): 128-row tiles, 2-stage, P hi-only ====
#define KPITCH 40
#define VPITCH 36
#define ST_KHI 0
#define ST_KLO 2560
#define ST_VHI 5120
#define ST_VLO 7424
#define STAGE_U 9728
#define ATTN_SMEM_BYTES (2 * STAGE_U * 4)     // 77824

__device__ __forceinline__ uint32_t h2u(half2 h) {
    return *reinterpret_cast<uint32_t*>(&h);
}

__device__ __forceinline__ void mma_f16(float c[4], const uint32_t a[4],
                                        uint32_t b0, uint32_t b1) {
    asm volatile(
        "mma.sync.aligned.m16n8k16.row.col.f32.f16.f16.f32 "
        "{%0,%1,%2,%3}, {%4,%5,%6,%7}, {%8,%9}, {%0,%1,%2,%3};"
        : "+f"(c[0]), "+f"(c[1]), "+f"(c[2]), "+f"(c[3])
        : "r"(a[0]), "r"(a[1]), "r"(a[2]), "r"(a[3]), "r"(b0), "r"(b1));
}

__global__ __launch_bounds__(256, 2) void attn_hmma_kernel() {
    extern __shared__ uint32_t smu[];

    const int qb = 15 - blockIdx.x;            // long CTAs first
    const int bh = blockIdx.y;
    const size_t base = (size_t)bh * SLEN * DKH;
    const __half* Khg = g_Kh + base;
    const __half* Klg = g_Kl + base;
    const __half* Vhg = g_Vh + base;
    const __half* Vlg = g_Vl + base;

    const int tid  = threadIdx.x;
    const int lane = tid & 31, warp = tid >> 5;
    const int g  = lane >> 2, tg = lane & 3;
    const int row0 = warp * 16;
    const uint32_t sb = smem_u32(smu);

#define ATTN_ISSUE(kb_, s_)                                                         \
    do {                                                                            \
        _Pragma("unroll")                                                           \
        for (int _j = 0; _j < 4; _j++) {                                            \
            int _t = tid + _j * 256;                                                \
            int _row = _t >> 4;                                                     \
            int _ch = _t & 15;                                                      \
            int _c7 = _ch & 7;                                                      \
            const __half* _ks = ((_ch < 8) ? Khg : Klg)                             \
                                + (size_t)((kb_) * 64 + _row) * DKH + _c7 * 8;      \
            cp16(sb + (uint32_t)((s_) * STAGE_U + ((_ch < 8) ? ST_KHI : ST_KLO)     \
                                  + _row * KPITCH + _c7 * 4) * 4, _ks);             \
            const __half* _vs = ((_ch < 8) ? Vhg : Vlg)                             \
                                + (size_t)((kb_) * 64 + _row) * DKH + _c7 * 8;      \
            cp16(sb + (uint32_t)((s_) * STAGE_U + ((_ch < 8) ? ST_VHI : ST_VLO)     \
                                  + _row * VPITCH + _c7 * 4) * 4, _vs);             \
        }                                                                           \
    } while (0)

    ATTN_ISSUE(0, 0); CP_COMMIT();
    ATTN_ISSUE(1, 1); CP_COMMIT();

    // ---- Q fragments -> registers (pair-permuted global, LDG.64) ----
    uint32_t qh[4][4], ql[4][4];
    {
        const uint32_t* Qg  = (const uint32_t*)g_Qh + (base >> 1)
                              + (size_t)(qb * 128 + row0 + g) * 32;
        const uint32_t* Qgl = (const uint32_t*)g_Ql + (base >> 1)
                              + (size_t)(qb * 128 + row0 + g) * 32;
#pragma unroll
        for (int ks = 0; ks < 4; ks++) {
            uint2 a0 = *(const uint2*)(Qg + ks * 8 + 2 * tg);
            uint2 a1 = *(const uint2*)(Qg + 8 * 32 + ks * 8 + 2 * tg);
            qh[ks][0] = a0.x; qh[ks][1] = a1.x; qh[ks][2] = a0.y; qh[ks][3] = a1.y;
            uint2 b0 = *(const uint2*)(Qgl + ks * 8 + 2 * tg);
            uint2 b1 = *(const uint2*)(Qgl + 8 * 32 + ks * 8 + 2 * tg);
            ql[ks][0] = b0.x; ql[ks][1] = b1.x; ql[ks][2] = b0.y; ql[ks][3] = b1.y;
        }
    }

    float acc_o[8][4];
#pragma unroll
    for (int j = 0; j < 8; j++)
#pragma unroll
        for (int t = 0; t < 4; t++) acc_o[j][t] = 0.f;
    float m_run[2] = {-1.0e30f, -1.0e30f};
    float l_run[2] = {0.f, 0.f};

    const int ntiles = 2 * (qb + 1);
    for (int kb = 0; kb < ntiles; kb++) {
        CP_WAIT(1);
        __syncthreads();

        const int s = kb & 1;
        const uint32_t* Khi_s = smu + s * STAGE_U + ST_KHI;
        const uint32_t* Klo_s = smu + s * STAGE_U + ST_KLO;
        const uint32_t vhiB = sb + (uint32_t)(s * STAGE_U + ST_VHI) * 4;
        const uint32_t vloB = sb + (uint32_t)(s * STAGE_U + ST_VLO) * 4;

        const bool active = (kb * 64 <= qb * 128 + row0 + 15);

        if (active) {
            // ---- S = Q K^T (3-term split) ----
            float s_acc[8][4];
#pragma unroll
            for (int j = 0; j < 8; j++)
#pragma unroll
                for (int t = 0; t < 4; t++) s_acc[j][t] = 0.f;

#pragma unroll
            for (int ks = 0; ks < 4; ks++) {
#pragma unroll
                for (int fn = 0; fn < 8; fn++) {
                    const int o = (fn * 8 + g) * KPITCH + ks * 8 + 2 * tg;
                    uint2 bh = *(const uint2*)(Khi_s + o);
                    uint2 bl = *(const uint2*)(Klo_s + o);
                    mma_f16(s_acc[fn], qh[ks], bh.x, bh.y);
                    mma_f16(s_acc[fn], qh[ks], bl.x, bl.y);
                    mma_f16(s_acc[fn], ql[ks], bh.x, bh.y);
                }
            }

            // ---- mask + online softmax (base-2) + pack P (hi only) ----
            uint32_t php[8][2];
            const bool diag = (kb >= 2 * qb);
#pragma unroll
            for (int h = 0; h < 2; h++) {
                if (diag) {
                    int row = qb * 128 + row0 + g + 8 * h;
#pragma unroll
                    for (int fn = 0; fn < 8; fn++) {
                        int col = kb * 64 + fn * 8 + 2 * tg;
                        if (col > row)     s_acc[fn][h * 2 + 0] = -1.0e30f;
                        if (col + 1 > row) s_acc[fn][h * 2 + 1] = -1.0e30f;
                    }
                }
                float mx = s_acc[0][h * 2];
#pragma unroll
                for (int fn = 0; fn < 8; fn++) {
                    mx = fmaxf(mx, s_acc[fn][h * 2 + 0]);
                    mx = fmaxf(mx, s_acc[fn][h * 2 + 1]);
                }
                mx = fmaxf(mx, __shfl_xor_sync(0xffffffffu, mx, 1));
                mx = fmaxf(mx, __shfl_xor_sync(0xffffffffu, mx, 2));
                float mn   = fmaxf(m_run[h], mx);
                float corr = exp2f(m_run[h] - mn);
                float rs = 0.f;
#pragma unroll
                for (int fn = 0; fn < 8; fn++) {
                    float p0 = exp2f(s_acc[fn][h * 2 + 0] - mn);
                    float p1 = exp2f(s_acc[fn][h * 2 + 1] - mn);
                    rs += p0 + p1;
                    php[fn][h] = h2u(__floats2half2_rn(p0, p1));
                }
                rs += __shfl_xor_sync(0xffffffffu, rs, 1);
                rs += __shfl_xor_sync(0xffffffffu, rs, 2);
                l_run[h] = l_run[h] * corr + rs;
                m_run[h] = mn;
#pragma unroll
                for (int fn = 0; fn < 8; fn++) {
                    acc_o[fn][h * 2 + 0] *= corr;
                    acc_o[fn][h * 2 + 1] *= corr;
                }
            }

            // ---- O += P V (P hi-only; V split hi/lo) ----
#pragma unroll
            for (int ks = 0; ks < 4; ks++) {
                uint32_t ahi[4] = { php[2 * ks][0], php[2 * ks][1],
                                    php[2 * ks + 1][0], php[2 * ks + 1][1] };
                const int vrow = ks * 16 + (lane & 15);
                const uint32_t abH = vhiB + (uint32_t)(vrow * VPITCH) * 4;
                const uint32_t abL = vloB + (uint32_t)(vrow * VPITCH) * 4;
#pragma unroll
                for (int fn = 0; fn < 8; fn++) {
                    uint2 bh = ldsm_x2_trans(abH + fn * 16);
                    uint2 bl = ldsm_x2_trans(abL + fn * 16);
                    mma_f16(acc_o[fn], ahi, bh.x, bh.y);
                    mma_f16(acc_o[fn], ahi, bl.x, bl.y);
                }
            }
        }

        __syncthreads();
        if (kb + 2 < ntiles) ATTN_ISSUE(kb + 2, s);
        CP_COMMIT();
    }
#undef ATTN_ISSUE

    // ---- normalize + write g_AOt in the NEW A-side permutation ----
    // slot within 32-k tile for k-local l of kg: (l&3)*8 + kg*2 + (l>>2)
    const int bb = bh >> 4, hh = bh & 15;
    const int j2 = tg >> 1;
    const int p0 = (((2 * tg) & 3) << 3) + j2;       // tg: 0,16,1,17
    const int p1 = (((2 * tg + 1) & 3) << 3) + j2;   // tg: 8,24,9,25
#pragma unroll
    for (int h = 0; h < 2; h++) {
        float invl = 1.0f / l_run[h];
        int row = qb * 128 + row0 + g + 8 * h;
        uint32_t* dst = g_AOt + ((size_t)bb * SLEN + row) * DMODEL + hh * DKH;
#pragma unroll
        for (int fn = 0; fn < 8; fn++) {
            int bidx = ((fn >> 2) << 5) + ((fn & 3) << 1);
            dst[bidx + p0] = f2tf32(acc_o[fn][h * 2 + 0] * invl);
            dst[bidx + p1] = f2tf32(acc_o[fn][h * 2 + 1] * invl);
        }
    }
}

// ---------------- launch -------------------------------------------------------
extern "C" void kernel_launch(void* const* d_in, const int* in_sizes, int n_in,
                              void* d_out, int out_size) {
    const float* q  = (const float*)d_in[0];
    const float* k  = (const float*)d_in[1];
    const float* v  = (const float*)d_in[2];
    // d_in[3] = mask (int32 tril) — causal, applied analytically
    const float* wq = (const float*)d_in[4];
    const float* bq = (const float*)d_in[5];
    const float* wk = (const float*)d_in[6];
    const float* bk = (const float*)d_in[7];
    const float* wv = (const float*)d_in[8];
    const float* bv = (const float*)d_in[9];
    const float* wo = (const float*)d_in[10];
    const float* bo = (const float*)d_in[11];
    float* out = (float*)d_out;

    cudaFuncSetAttribute(qkv_tf32_kernel, cudaFuncAttributeMaxDynamicSharedMemorySize, GEMM_SMEM);
    cudaFuncSetAttribute(outproj_tf32_kernel, cudaFuncAttributeMaxDynamicSharedMemorySize, GEMM_SMEM);
    cudaFuncSetAttribute(attn_hmma_kernel, cudaFuncAttributeMaxDynamicSharedMemorySize, ATTN_SMEM_BYTES);

    conv_all_kernel<<<14336, 256>>>(q, k, v, wq, wk, wv, wo);

    qkv_tf32_kernel<<<dim3(DMODEL / 128, MTOT / 128, 3), 256, GEMM_SMEM>>>(bq, bk, bv);

    attn_hmma_kernel<<<dim3(SLEN / 128, NB * NHEAD), 256, ATTN_SMEM_BYTES>>>();

    outproj_tf32_kernel<<<dim3(DMODEL / 128, MTOT / 128), 256, GEMM_SMEM>>>(bo, out);
}

// round 13
// speedup vs baseline: 1.7853x; 1.0700x over previous
#include <cuda_runtime.h>
#include <cuda_fp16.h>
#include <cstdint>

#define SLEN    2048
#define DMODEL  1024
#define NHEAD   16
#define DKH     64
#define NB      4
#define MTOT    (NB * SLEN)     // 8192

// ---------------- scratch (allocation-free: __device__ globals) ----------------
// pre-split fp16 hi/lo Q/K/V, layout [B,H,S,64].
// Q is pre-scaled by 0.125*log2(e); Q and K are d-PAIR-PERMUTED; V is natural.
__device__ __half g_Qh[(size_t)NB * NHEAD * SLEN * DKH];
__device__ __half g_Ql[(size_t)NB * NHEAD * SLEN * DKH];
__device__ __half g_Kh[(size_t)NB * NHEAD * SLEN * DKH];
__device__ __half g_Kl[(size_t)NB * NHEAD * SLEN * DKH];
__device__ __half g_Vh[(size_t)NB * NHEAD * SLEN * DKH];
__device__ __half g_Vl[(size_t)NB * NHEAD * SLEN * DKH];

// pre-converted tf32 operands, pair-permuted within each 8-k group:
// u32 order per group = [k0,k4,k1,k5,k2,k6,k3,k7]
__device__ uint32_t g_Xt[(size_t)3 * MTOT * DMODEL];     // q,k,v inputs
__device__ uint32_t g_Wt[(size_t)4 * DMODEL * DMODEL];   // wq,wk,wv,wo
__device__ uint32_t g_AOt[(size_t)MTOT * DMODEL];        // attn out, tf32 permuted

// ---------------- helpers ------------------------------------------------------
__device__ __forceinline__ uint32_t f2tf32(float f) {
    uint32_t u;
    asm("cvt.rna.tf32.f32 %0, %1;" : "=r"(u) : "f"(f));
    return u;
}

__device__ __forceinline__ void mma_tf32(float c[4], const uint32_t a[4], const uint32_t b[2]) {
    asm volatile(
        "mma.sync.aligned.m16n8k8.row.col.f32.tf32.tf32.f32 "
        "{%0,%1,%2,%3}, {%4,%5,%6,%7}, {%8,%9}, {%0,%1,%2,%3};"
        : "+f"(c[0]), "+f"(c[1]), "+f"(c[2]), "+f"(c[3])
        : "r"(a[0]), "r"(a[1]), "r"(a[2]), "r"(a[3]), "r"(b[0]), "r"(b[1]));
}

__device__ __forceinline__ uint32_t smem_u32(const void* p) {
    uint32_t a;
    asm("{ .reg .u64 t; cvta.to.shared.u64 t, %1; cvt.u32.u64 %0, t; }" : "=r"(a) : "l"(p));
    return a;
}

__device__ __forceinline__ void cp16(uint32_t dst, const void* src) {
    asm volatile("cp.async.cg.shared.global [%0], [%1], 16;" :: "r"(dst), "l"(src));
}
#define CP_COMMIT() asm volatile("cp.async.commit_group;")
#define CP_WAIT(n)  asm volatile("cp.async.wait_group %0;" :: "n"(n))

__device__ __forceinline__ uint2 ldsm_x2_trans(uint32_t addr) {
    uint2 r;
    asm volatile("ldmatrix.sync.aligned.m8n8.x2.trans.shared.b16 {%0,%1}, [%2];"
                 : "=r"(r.x), "=r"(r.y) : "r"(addr));
    return r;
}

// ---------------- fused tf32 pre-convert (all 7 tensors, one launch) -----------
__global__ __launch_bounds__(256) void conv_all_kernel(
    const float* __restrict__ q, const float* __restrict__ k, const float* __restrict__ v,
    const float* __restrict__ wq, const float* __restrict__ wk,
    const float* __restrict__ wv, const float* __restrict__ wo)
{
    int b = blockIdx.x;
    const float* src;
    uint32_t* dst;
    int i;
    if (b < 12288) {
        int sel = b >> 12;
        src = (sel == 0) ? q : (sel == 1) ? k : v;
        dst = g_Xt + (size_t)sel * MTOT * DMODEL;
        i = (b & 4095) * 256 + threadIdx.x;
    } else {
        int sel = (b - 12288) >> 9;
        src = (sel == 0) ? wq : (sel == 1) ? wk : (sel == 2) ? wv : wo;
        dst = g_Wt + (size_t)sel * DMODEL * DMODEL;
        i = ((b - 12288) & 511) * 256 + threadIdx.x;
    }
    const float4* s4 = (const float4*)src;
    uint4* d4 = (uint4*)dst;
    float4 v0 = s4[2 * i];
    float4 v1 = s4[2 * i + 1];
    uint4 o0, o1;
    o0.x = f2tf32(v0.x); o0.y = f2tf32(v1.x);   // k0,k4
    o0.z = f2tf32(v0.y); o0.w = f2tf32(v1.y);   // k1,k5
    o1.x = f2tf32(v0.z); o1.y = f2tf32(v1.z);   // k2,k6
    o1.z = f2tf32(v0.w); o1.w = f2tf32(v1.w);   // k3,k7
    d4[2 * i]     = o0;
    d4[2 * i + 1] = o1;
}

// ======================= tf32 tensor-core GEMM (R9 config) =====================
// 128x128 CTA tile, 256 threads (2m x 4n warps, warp tile 64x32), BK=32, 2-stage.
#define BK2 32
#define P40 40
#define STAGEU (128 * P40)                    // u32 per operand per stage
#define GEMM_SMEM (2 * 2 * STAGEU * 4)        // 81920 bytes

__device__ __forceinline__ void gemm_tf32_main(const uint32_t* __restrict__ X,
                                               const uint32_t* __restrict__ W,
                                               int m0, int n0,
                                               float acc[4][4][4]) {
    extern __shared__ uint32_t su[];
    const int tid  = threadIdx.x;
    const int lane = tid & 31, warp = tid >> 5;
    const int wm = warp >> 2, wn = warp & 3;
    const int g  = lane >> 2, tg = lane & 3;

    const uint32_t sb = smem_u32(su);

#define ISSUE_TILE(kt, s)                                                           \
    do {                                                                            \
        uint32_t _b = sb + ((uint32_t)(s) * 2 * STAGEU) * 4u;                       \
        _Pragma("unroll")                                                           \
        for (int _j = 0; _j < 4; _j++) {                                            \
            int _seg = tid + _j * 256;                                              \
            int _row = _seg >> 3;                                                   \
            int _ch  = _seg & 7;                                                    \
            uint32_t _off = (uint32_t)(_row * P40 * 4 + _ch * 16);                  \
            cp16(_b + _off,                                                         \
                 (const char*)(X + (size_t)(m0 + _row) * DMODEL + (kt) * BK2) + _ch * 16); \
            cp16(_b + (uint32_t)(STAGEU * 4) + _off,                                \
                 (const char*)(W + (size_t)(n0 + _row) * DMODEL + (kt) * BK2) + _ch * 16); \
        }                                                                           \
    } while (0)

    const int NT = DMODEL / BK2;              // 32
    ISSUE_TILE(0, 0); CP_COMMIT();
    ISSUE_TILE(1, 1); CP_COMMIT();

    for (int kt = 0; kt < NT; kt++) {
        CP_WAIT(1);
        __syncthreads();

        const int s = kt & 1;
        const uint32_t* Asb = su + s * 2 * STAGEU;
        const uint32_t* Bsb = Asb + STAGEU;

#pragma unroll
        for (int kg = 0; kg < 4; kg++) {
            const int colb = kg * 8 + 2 * tg;
            uint32_t a[4][4], b[4][2];
#pragma unroll
            for (int fm = 0; fm < 4; fm++) {
                const int r = wm * 64 + fm * 16 + g;
                uint2 t0 = *(const uint2*)(Asb + r * P40 + colb);
                uint2 t1 = *(const uint2*)(Asb + (r + 8) * P40 + colb);
                a[fm][0] = t0.x; a[fm][2] = t0.y;
                a[fm][1] = t1.x; a[fm][3] = t1.y;
            }
#pragma unroll
            for (int fn = 0; fn < 4; fn++) {
                const int r = wn * 32 + fn * 8 + g;
                uint2 t = *(const uint2*)(Bsb + r * P40 + colb);
                b[fn][0] = t.x; b[fn][1] = t.y;
            }
#pragma unroll
            for (int fm = 0; fm < 4; fm++)
#pragma unroll
                for (int fn = 0; fn < 4; fn++)
                    mma_tf32(acc[fm][fn], a[fm], b[fn]);
        }

        __syncthreads();
        if (kt + 2 < NT) ISSUE_TILE(kt + 2, s);
        CP_COMMIT();
    }
#undef ISSUE_TILE
}

// ---------------- QKV projection -> pre-split fp16 hi/lo -----------------------
#define QSCALE 0.180336880f

__global__ __launch_bounds__(256, 2) void qkv_tf32_kernel(
    const float* __restrict__ bq, const float* __restrict__ bk, const float* __restrict__ bv)
{
    const int z = blockIdx.z;
    const uint32_t* X = g_Xt + (size_t)z * MTOT * DMODEL;
    const uint32_t* W = g_Wt + (size_t)z * DMODEL * DMODEL;
    const float* Bb   = (z == 0) ? bq : (z == 1) ? bk : bv;
    __half* Hh        = (z == 0) ? g_Qh : (z == 1) ? g_Kh : g_Vh;
    __half* Hl        = (z == 0) ? g_Ql : (z == 1) ? g_Kl : g_Vl;
    const float scale = (z == 0) ? QSCALE : 1.0f;

    const int m0 = blockIdx.y * 128, n0 = blockIdx.x * 128;
    float acc[4][4][4];
#pragma unroll
    for (int i = 0; i < 4; i++)
#pragma unroll
        for (int j = 0; j < 4; j++)
#pragma unroll
            for (int t = 0; t < 4; t++) acc[i][j][t] = 0.f;

    gemm_tf32_main(X, W, m0, n0, acc);

    const int tid  = threadIdx.x;
    const int lane = tid & 31, warp = tid >> 5;
    const int wm = warp >> 2, wn = warp & 3;
    const int g  = lane >> 2, tg = lane & 3;

#pragma unroll
    for (int fn = 0; fn < 4; fn++) {
        const int n  = n0 + wn * 32 + fn * 8 + 2 * tg;
        const int hh = n >> 6, dd = n & 63;
        int ddw;
        if (z < 2) {
            int kk  = dd >> 1;
            int grp = kk >> 3, pig = kk & 7;
            int pp  = ((pig & 3) << 1) | (pig >> 2);
            ddw = (grp * 8 + pp) * 2;
        } else {
            ddw = dd;
        }
        const float b0 = Bb[n], b1 = Bb[n + 1];
#pragma unroll
        for (int fm = 0; fm < 4; fm++) {
#pragma unroll
            for (int half_ = 0; half_ < 2; half_++) {
                const int m  = m0 + wm * 64 + fm * 16 + g + half_ * 8;
                const int bb = m >> 11;
                const int ss = m & (SLEN - 1);
                float v0 = (acc[fm][fn][half_ * 2 + 0] + b0) * scale;
                float v1 = (acc[fm][fn][half_ * 2 + 1] + b1) * scale;
                half2 hi = __floats2half2_rn(v0, v1);
                half2 lo = __floats2half2_rn(v0 - __low2float(hi), v1 - __high2float(hi));
                size_t idx = (((size_t)bb * NHEAD + hh) * SLEN + ss) * DKH + ddw;
                *(half2*)(Hh + idx) = hi;
                *(half2*)(Hl + idx) = lo;
            }
        }
    }
}

// ---------------- output projection -------------------------------------------
__global__ __launch_bounds__(256, 2) void outproj_tf32_kernel(
    const float* __restrict__ Bb, float* __restrict__ Out)
{
    const uint32_t* W = g_Wt + (size_t)3 * DMODEL * DMODEL;
    const int m0 = blockIdx.y * 128, n0 = blockIdx.x * 128;
    float acc[4][4][4];
#pragma unroll
    for (int i = 0; i < 4; i++)
#pragma unroll
        for (int j = 0; j < 4; j++)
#pragma unroll
            for (int t = 0; t < 4; t++) acc[i][j][t] = 0.f;

    gemm_tf32_main(g_AOt, W, m0, n0, acc);

    const int tid  = threadIdx.x;
    const int lane = tid & 31, warp = tid >> 5;
    const int wm = warp >> 2, wn = warp & 3;
    const int g  = lane >> 2, tg = lane & 3;

#pragma unroll
    for (int fn = 0; fn < 4; fn++) {
        const int n = n0 + wn * 32 + fn * 8 + 2 * tg;
        const float b0 = Bb[n], b1 = Bb[n + 1];
#pragma unroll
        for (int fm = 0; fm < 4; fm++) {
#pragma unroll
            for (int half_ = 0; half_ < 2; half_++) {
                const int m = m0 + wm * 64 + fm * 16 + g + half_ * 8;
                *(float2*)(Out + (size_t)m * DMODEL + n) =
                    make_float2(acc[fm][fn][half_ * 2 + 0] + b0,
                                acc[fm][fn][half_ * 2 + 1] + b1);
            }
        }
    }
}

// ============ Flash attention: 128-row tiles, 2-stage, P hi-only ===============
#define KPITCH 40
#define VPITCH 36
#define ST_KHI 0
#define ST_KLO 2560
#define ST_VHI 5120
#define ST_VLO 7424
#define STAGE_U 9728
#define ATTN_SMEM_BYTES (2 * STAGE_U * 4)     // 77824

__device__ __forceinline__ uint32_t h2u(half2 h) {
    return *reinterpret_cast<uint32_t*>(&h);
}

__device__ __forceinline__ void mma_f16(float c[4], const uint32_t a[4],
                                        uint32_t b0, uint32_t b1) {
    asm volatile(
        "mma.sync.aligned.m16n8k16.row.col.f32.f16.f16.f32 "
        "{%0,%1,%2,%3}, {%4,%5,%6,%7}, {%8,%9}, {%0,%1,%2,%3};"
        : "+f"(c[0]), "+f"(c[1]), "+f"(c[2]), "+f"(c[3])
        : "r"(a[0]), "r"(a[1]), "r"(a[2]), "r"(a[3]), "r"(b0), "r"(b1));
}

__global__ __launch_bounds__(256, 2) void attn_hmma_kernel() {
    extern __shared__ uint32_t smu[];

    const int qb = 15 - blockIdx.x;            // long CTAs first
    const int bh = blockIdx.y;
    const size_t base = (size_t)bh * SLEN * DKH;
    const __half* Khg = g_Kh + base;
    const __half* Klg = g_Kl + base;
    const __half* Vhg = g_Vh + base;
    const __half* Vlg = g_Vl + base;

    const int tid  = threadIdx.x;
    const int lane = tid & 31, warp = tid >> 5;
    const int g  = lane >> 2, tg = lane & 3;
    const int row0 = warp * 16;
    const uint32_t sb = smem_u32(smu);

#define ATTN_ISSUE(kb_, s_)                                                         \
    do {                                                                            \
        _Pragma("unroll")                                                           \
        for (int _j = 0; _j < 4; _j++) {                                            \
            int _t = tid + _j * 256;                                                \
            int _row = _t >> 4;                                                     \
            int _ch = _t & 15;                                                      \
            int _c7 = _ch & 7;                                                      \
            const __half* _ks = ((_ch < 8) ? Khg : Klg)                             \
                                + (size_t)((kb_) * 64 + _row) * DKH + _c7 * 8;      \
            cp16(sb + (uint32_t)((s_) * STAGE_U + ((_ch < 8) ? ST_KHI : ST_KLO)     \
                                  + _row * KPITCH + _c7 * 4) * 4, _ks);             \
            const __half* _vs = ((_ch < 8) ? Vhg : Vlg)                             \
                                + (size_t)((kb_) * 64 + _row) * DKH + _c7 * 8;      \
            cp16(sb + (uint32_t)((s_) * STAGE_U + ((_ch < 8) ? ST_VHI : ST_VLO)     \
                                  + _row * VPITCH + _c7 * 4) * 4, _vs);             \
        }                                                                           \
    } while (0)

    ATTN_ISSUE(0, 0); CP_COMMIT();
    ATTN_ISSUE(1, 1); CP_COMMIT();

    // ---- Q fragments -> registers (pair-permuted global, LDG.64) ----
    uint32_t qh[4][4], ql[4][4];
    {
        const uint32_t* Qg  = (const uint32_t*)g_Qh + (base >> 1)
                              + (size_t)(qb * 128 + row0 + g) * 32;
        const uint32_t* Qgl = (const uint32_t*)g_Ql + (base >> 1)
                              + (size_t)(qb * 128 + row0 + g) * 32;
#pragma unroll
        for (int ks = 0; ks < 4; ks++) {
            uint2 a0 = *(const uint2*)(Qg + ks * 8 + 2 * tg);
            uint2 a1 = *(const uint2*)(Qg + 8 * 32 + ks * 8 + 2 * tg);
            qh[ks][0] = a0.x; qh[ks][1] = a1.x; qh[ks][2] = a0.y; qh[ks][3] = a1.y;
            uint2 b0 = *(const uint2*)(Qgl + ks * 8 + 2 * tg);
            uint2 b1 = *(const uint2*)(Qgl + 8 * 32 + ks * 8 + 2 * tg);
            ql[ks][0] = b0.x; ql[ks][1] = b1.x; ql[ks][2] = b0.y; ql[ks][3] = b1.y;
        }
    }

    float acc_o[8][4];
#pragma unroll
    for (int j = 0; j < 8; j++)
#pragma unroll
        for (int t = 0; t < 4; t++) acc_o[j][t] = 0.f;
    float m_run[2] = {-1.0e30f, -1.0e30f};
    float l_run[2] = {0.f, 0.f};

    const int ntiles = 2 * (qb + 1);
    for (int kb = 0; kb < ntiles; kb++) {
        CP_WAIT(1);
        __syncthreads();

        const int s = kb & 1;
        const uint32_t* Khi_s = smu + s * STAGE_U + ST_KHI;
        const uint32_t* Klo_s = smu + s * STAGE_U + ST_KLO;
        const uint32_t vhiB = sb + (uint32_t)(s * STAGE_U + ST_VHI) * 4;
        const uint32_t vloB = sb + (uint32_t)(s * STAGE_U + ST_VLO) * 4;

        const bool active = (kb * 64 <= qb * 128 + row0 + 15);

        if (active) {
            // ---- S = Q K^T (3-term split) ----
            float s_acc[8][4];
#pragma unroll
            for (int j = 0; j < 8; j++)
#pragma unroll
                for (int t = 0; t < 4; t++) s_acc[j][t] = 0.f;

#pragma unroll
            for (int ks = 0; ks < 4; ks++) {
#pragma unroll
                for (int fn = 0; fn < 8; fn++) {
                    const int o = (fn * 8 + g) * KPITCH + ks * 8 + 2 * tg;
                    uint2 bh = *(const uint2*)(Khi_s + o);
                    uint2 bl = *(const uint2*)(Klo_s + o);
                    mma_f16(s_acc[fn], qh[ks], bh.x, bh.y);
                    mma_f16(s_acc[fn], qh[ks], bl.x, bl.y);
                    mma_f16(s_acc[fn], ql[ks], bh.x, bh.y);
                }
            }

            // ---- mask + online softmax (base-2) + pack P (hi only) ----
            uint32_t php[8][2];
            const bool diag = (kb >= 2 * qb);
#pragma unroll
            for (int h = 0; h < 2; h++) {
                if (diag) {
                    int row = qb * 128 + row0 + g + 8 * h;
#pragma unroll
                    for (int fn = 0; fn < 8; fn++) {
                        int col = kb * 64 + fn * 8 + 2 * tg;
                        if (col > row)     s_acc[fn][h * 2 + 0] = -1.0e30f;
                        if (col + 1 > row) s_acc[fn][h * 2 + 1] = -1.0e30f;
                    }
                }
                float mx = s_acc[0][h * 2];
#pragma unroll
                for (int fn = 0; fn < 8; fn++) {
                    mx = fmaxf(mx, s_acc[fn][h * 2 + 0]);
                    mx = fmaxf(mx, s_acc[fn][h * 2 + 1]);
                }
                mx = fmaxf(mx, __shfl_xor_sync(0xffffffffu, mx, 1));
                mx = fmaxf(mx, __shfl_xor_sync(0xffffffffu, mx, 2));
                float mn   = fmaxf(m_run[h], mx);
                float corr = exp2f(m_run[h] - mn);
                float rs = 0.f;
#pragma unroll
                for (int fn = 0; fn < 8; fn++) {
                    float p0 = exp2f(s_acc[fn][h * 2 + 0] - mn);
                    float p1 = exp2f(s_acc[fn][h * 2 + 1] - mn);
                    rs += p0 + p1;
                    php[fn][h] = h2u(__floats2half2_rn(p0, p1));
                }
                rs += __shfl_xor_sync(0xffffffffu, rs, 1);
                rs += __shfl_xor_sync(0xffffffffu, rs, 2);
                l_run[h] = l_run[h] * corr + rs;
                m_run[h] = mn;
#pragma unroll
                for (int fn = 0; fn < 8; fn++) {
                    acc_o[fn][h * 2 + 0] *= corr;
                    acc_o[fn][h * 2 + 1] *= corr;
                }
            }

            // ---- O += P V (P hi-only; V split hi/lo) ----
#pragma unroll
            for (int ks = 0; ks < 4; ks++) {
                uint32_t ahi[4] = { php[2 * ks][0], php[2 * ks][1],
                                    php[2 * ks + 1][0], php[2 * ks + 1][1] };
                const int vrow = ks * 16 + (lane & 15);
                const uint32_t abH = vhiB + (uint32_t)(vrow * VPITCH) * 4;
                const uint32_t abL = vloB + (uint32_t)(vrow * VPITCH) * 4;
#pragma unroll
                for (int fn = 0; fn < 8; fn++) {
                    uint2 bh = ldsm_x2_trans(abH + fn * 16);
                    uint2 bl = ldsm_x2_trans(abL + fn * 16);
                    mma_f16(acc_o[fn], ahi, bh.x, bh.y);
                    mma_f16(acc_o[fn], ahi, bl.x, bl.y);
                }
            }
        }

        __syncthreads();
        if (kb + 2 < ntiles) ATTN_ISSUE(kb + 2, s);
        CP_COMMIT();
    }
#undef ATTN_ISSUE

    // ---- normalize + write tf32 pair-permuted AO (R9 permutation) ----
    const int bb = bh >> 4, hh = bh & 15;
    const int kk0 = 2 * tg, kk1 = 2 * tg + 1;
    const int p0 = ((kk0 & 3) << 1) | (kk0 >> 2);
    const int p1 = ((kk1 & 3) << 1) | (kk1 >> 2);
#pragma unroll
    for (int h = 0; h < 2; h++) {
        float invl = 1.0f / l_run[h];
        int row = qb * 128 + row0 + g + 8 * h;
        uint32_t* dst = g_AOt + ((size_t)bb * SLEN + row) * DMODEL + hh * DKH;
#pragma unroll
        for (int fn = 0; fn < 8; fn++) {
            dst[fn * 8 + p0] = f2tf32(acc_o[fn][h * 2 + 0] * invl);
            dst[fn * 8 + p1] = f2tf32(acc_o[fn][h * 2 + 1] * invl);
        }
    }
}

// ---------------- launch -------------------------------------------------------
extern "C" void kernel_launch(void* const* d_in, const int* in_sizes, int n_in,
                              void* d_out, int out_size) {
    const float* q  = (const float*)d_in[0];
    const float* k  = (const float*)d_in[1];
    const float* v  = (const float*)d_in[2];
    // d_in[3] = mask (int32 tril) — causal, applied analytically
    const float* wq = (const float*)d_in[4];
    const float* bq = (const float*)d_in[5];
    const float* wk = (const float*)d_in[6];
    const float* bk = (const float*)d_in[7];
    const float* wv = (const float*)d_in[8];
    const float* bv = (const float*)d_in[9];
    const float* wo = (const float*)d_in[10];
    const float* bo = (const float*)d_in[11];
    float* out = (float*)d_out;

    cudaFuncSetAttribute(qkv_tf32_kernel, cudaFuncAttributeMaxDynamicSharedMemorySize, GEMM_SMEM);
    cudaFuncSetAttribute(outproj_tf32_kernel, cudaFuncAttributeMaxDynamicSharedMemorySize, GEMM_SMEM);
    cudaFuncSetAttribute(attn_hmma_kernel, cudaFuncAttributeMaxDynamicSharedMemorySize, ATTN_SMEM_BYTES);

    conv_all_kernel<<<14336, 256>>>(q, k, v, wq, wk, wv, wo);

    qkv_tf32_kernel<<<dim3(DMODEL / 128, MTOT / 128, 3), 256, GEMM_SMEM>>>(bq, bk, bv);

    attn_hmma_kernel<<<dim3(SLEN / 128, NB * NHEAD), 256, ATTN_SMEM_BYTES>>>();

    outproj_tf32_kernel<<<dim3(DMODEL / 128, MTOT / 128), 256, GEMM_SMEM>>>(bo, out);
}

// round 14
// speedup vs baseline: 1.9324x; 1.0824x over previous
#include <cuda_runtime.h>
#include <cuda_fp16.h>
#include <cstdint>

#define SLEN    2048
#define DMODEL  1024
#define NHEAD   16
#define DKH     64
#define NB      4
#define MTOT    (NB * SLEN)     // 8192

// ---------------- scratch (allocation-free: __device__ globals) ----------------
// pre-split fp16 hi/lo Q/K (V hi-only), layout [B,H,S,64].
// Q is pre-scaled by 0.125*log2(e); Q and K are d-PAIR-PERMUTED; V is natural.
__device__ __half g_Qh[(size_t)NB * NHEAD * SLEN * DKH];
__device__ __half g_Ql[(size_t)NB * NHEAD * SLEN * DKH];
__device__ __half g_Kh[(size_t)NB * NHEAD * SLEN * DKH];
__device__ __half g_Kl[(size_t)NB * NHEAD * SLEN * DKH];
__device__ __half g_Vh[(size_t)NB * NHEAD * SLEN * DKH];

// pre-converted tf32 operands, pair-permuted within each 8-k group:
// u32 order per group = [k0,k4,k1,k5,k2,k6,k3,k7]
__device__ uint32_t g_Xt[(size_t)3 * MTOT * DMODEL];     // q,k,v inputs
__device__ uint32_t g_Wt[(size_t)4 * DMODEL * DMODEL];   // wq,wk,wv,wo
__device__ uint32_t g_AOt[(size_t)MTOT * DMODEL];        // attn out, tf32 permuted

// ---------------- helpers ------------------------------------------------------
__device__ __forceinline__ uint32_t f2tf32(float f) {
    uint32_t u;
    asm("cvt.rna.tf32.f32 %0, %1;" : "=r"(u) : "f"(f));
    return u;
}

__device__ __forceinline__ void mma_tf32(float c[4], const uint32_t a[4], const uint32_t b[2]) {
    asm volatile(
        "mma.sync.aligned.m16n8k8.row.col.f32.tf32.tf32.f32 "
        "{%0,%1,%2,%3}, {%4,%5,%6,%7}, {%8,%9}, {%0,%1,%2,%3};"
        : "+f"(c[0]), "+f"(c[1]), "+f"(c[2]), "+f"(c[3])
        : "r"(a[0]), "r"(a[1]), "r"(a[2]), "r"(a[3]), "r"(b[0]), "r"(b[1]));
}

__device__ __forceinline__ uint32_t smem_u32(const void* p) {
    uint32_t a;
    asm("{ .reg .u64 t; cvta.to.shared.u64 t, %1; cvt.u32.u64 %0, t; }" : "=r"(a) : "l"(p));
    return a;
}

__device__ __forceinline__ void cp16(uint32_t dst, const void* src) {
    asm volatile("cp.async.cg.shared.global [%0], [%1], 16;" :: "r"(dst), "l"(src));
}
#define CP_COMMIT() asm volatile("cp.async.commit_group;")
#define CP_WAIT(n)  asm volatile("cp.async.wait_group %0;" :: "n"(n))

__device__ __forceinline__ uint2 ldsm_x2_trans(uint32_t addr) {
    uint2 r;
    asm volatile("ldmatrix.sync.aligned.m8n8.x2.trans.shared.b16 {%0,%1}, [%2];"
                 : "=r"(r.x), "=r"(r.y) : "r"(addr));
    return r;
}

// ---------------- fused tf32 pre-convert (all 7 tensors, one launch) -----------
__global__ __launch_bounds__(256) void conv_all_kernel(
    const float* __restrict__ q, const float* __restrict__ k, const float* __restrict__ v,
    const float* __restrict__ wq, const float* __restrict__ wk,
    const float* __restrict__ wv, const float* __restrict__ wo)
{
    int b = blockIdx.x;
    const float* src;
    uint32_t* dst;
    int i;
    if (b < 12288) {
        int sel = b >> 12;
        src = (sel == 0) ? q : (sel == 1) ? k : v;
        dst = g_Xt + (size_t)sel * MTOT * DMODEL;
        i = (b & 4095) * 256 + threadIdx.x;
    } else {
        int sel = (b - 12288) >> 9;
        src = (sel == 0) ? wq : (sel == 1) ? wk : (sel == 2) ? wv : wo;
        dst = g_Wt + (size_t)sel * DMODEL * DMODEL;
        i = ((b - 12288) & 511) * 256 + threadIdx.x;
    }
    const float4* s4 = (const float4*)src;
    uint4* d4 = (uint4*)dst;
    float4 v0 = s4[2 * i];
    float4 v1 = s4[2 * i + 1];
    uint4 o0, o1;
    o0.x = f2tf32(v0.x); o0.y = f2tf32(v1.x);   // k0,k4
    o0.z = f2tf32(v0.y); o0.w = f2tf32(v1.y);   // k1,k5
    o1.x = f2tf32(v0.z); o1.y = f2tf32(v1.z);   // k2,k6
    o1.z = f2tf32(v0.w); o1.w = f2tf32(v1.w);   // k3,k7
    d4[2 * i]     = o0;
    d4[2 * i + 1] = o1;
}

// ======================= tf32 tensor-core GEMM (R9 config) =====================
// 128x128 CTA tile, 256 threads (2m x 4n warps, warp tile 64x32), BK=32, 2-stage.
#define BK2 32
#define P40 40
#define STAGEU (128 * P40)                    // u32 per operand per stage
#define GEMM_SMEM (2 * 2 * STAGEU * 4)        // 81920 bytes

__device__ __forceinline__ void gemm_tf32_main(const uint32_t* __restrict__ X,
                                               const uint32_t* __restrict__ W,
                                               int m0, int n0,
                                               float acc[4][4][4]) {
    extern __shared__ uint32_t su[];
    const int tid  = threadIdx.x;
    const int lane = tid & 31, warp = tid >> 5;
    const int wm = warp >> 2, wn = warp & 3;
    const int g  = lane >> 2, tg = lane & 3;

    const uint32_t sb = smem_u32(su);

#define ISSUE_TILE(kt, s)                                                           \
    do {                                                                            \
        uint32_t _b = sb + ((uint32_t)(s) * 2 * STAGEU) * 4u;                       \
        _Pragma("unroll")                                                           \
        for (int _j = 0; _j < 4; _j++) {                                            \
            int _seg = tid + _j * 256;                                              \
            int _row = _seg >> 3;                                                   \
            int _ch  = _seg & 7;                                                    \
            uint32_t _off = (uint32_t)(_row * P40 * 4 + _ch * 16);                  \
            cp16(_b + _off,                                                         \
                 (const char*)(X + (size_t)(m0 + _row) * DMODEL + (kt) * BK2) + _ch * 16); \
            cp16(_b + (uint32_t)(STAGEU * 4) + _off,                                \
                 (const char*)(W + (size_t)(n0 + _row) * DMODEL + (kt) * BK2) + _ch * 16); \
        }                                                                           \
    } while (0)

    const int NT = DMODEL / BK2;              // 32
    ISSUE_TILE(0, 0); CP_COMMIT();
    ISSUE_TILE(1, 1); CP_COMMIT();

    for (int kt = 0; kt < NT; kt++) {
        CP_WAIT(1);
        __syncthreads();

        const int s = kt & 1;
        const uint32_t* Asb = su + s * 2 * STAGEU;
        const uint32_t* Bsb = Asb + STAGEU;

#pragma unroll
        for (int kg = 0; kg < 4; kg++) {
            const int colb = kg * 8 + 2 * tg;
            uint32_t a[4][4], b[4][2];
#pragma unroll
            for (int fm = 0; fm < 4; fm++) {
                const int r = wm * 64 + fm * 16 + g;
                uint2 t0 = *(const uint2*)(Asb + r * P40 + colb);
                uint2 t1 = *(const uint2*)(Asb + (r + 8) * P40 + colb);
                a[fm][0] = t0.x; a[fm][2] = t0.y;
                a[fm][1] = t1.x; a[fm][3] = t1.y;
            }
#pragma unroll
            for (int fn = 0; fn < 4; fn++) {
                const int r = wn * 32 + fn * 8 + g;
                uint2 t = *(const uint2*)(Bsb + r * P40 + colb);
                b[fn][0] = t.x; b[fn][1] = t.y;
            }
#pragma unroll
            for (int fm = 0; fm < 4; fm++)
#pragma unroll
                for (int fn = 0; fn < 4; fn++)
                    mma_tf32(acc[fm][fn], a[fm], b[fn]);
        }

        __syncthreads();
        if (kt + 2 < NT) ISSUE_TILE(kt + 2, s);
        CP_COMMIT();
    }
#undef ISSUE_TILE
}

// ---------------- QKV projection -> pre-split fp16 hi/lo (V hi-only) -----------
#define QSCALE 0.180336880f

__global__ __launch_bounds__(256, 2) void qkv_tf32_kernel(
    const float* __restrict__ bq, const float* __restrict__ bk, const float* __restrict__ bv)
{
    const int z = blockIdx.z;
    const uint32_t* X = g_Xt + (size_t)z * MTOT * DMODEL;
    const uint32_t* W = g_Wt + (size_t)z * DMODEL * DMODEL;
    const float* Bb   = (z == 0) ? bq : (z == 1) ? bk : bv;
    __half* Hh        = (z == 0) ? g_Qh : (z == 1) ? g_Kh : g_Vh;
    __half* Hl        = (z == 0) ? g_Ql : g_Kl;   // unused for z==2
    const float scale = (z == 0) ? QSCALE : 1.0f;

    const int m0 = blockIdx.y * 128, n0 = blockIdx.x * 128;
    float acc[4][4][4];
#pragma unroll
    for (int i = 0; i < 4; i++)
#pragma unroll
        for (int j = 0; j < 4; j++)
#pragma unroll
            for (int t = 0; t < 4; t++) acc[i][j][t] = 0.f;

    gemm_tf32_main(X, W, m0, n0, acc);

    const int tid  = threadIdx.x;
    const int lane = tid & 31, warp = tid >> 5;
    const int wm = warp >> 2, wn = warp & 3;
    const int g  = lane >> 2, tg = lane & 3;

#pragma unroll
    for (int fn = 0; fn < 4; fn++) {
        const int n  = n0 + wn * 32 + fn * 8 + 2 * tg;
        const int hh = n >> 6, dd = n & 63;
        int ddw;
        if (z < 2) {
            int kk  = dd >> 1;
            int grp = kk >> 3, pig = kk & 7;
            int pp  = ((pig & 3) << 1) | (pig >> 2);
            ddw = (grp * 8 + pp) * 2;
        } else {
            ddw = dd;
        }
        const float b0 = Bb[n], b1 = Bb[n + 1];
#pragma unroll
        for (int fm = 0; fm < 4; fm++) {
#pragma unroll
            for (int half_ = 0; half_ < 2; half_++) {
                const int m  = m0 + wm * 64 + fm * 16 + g + half_ * 8;
                const int bb = m >> 11;
                const int ss = m & (SLEN - 1);
                float v0 = (acc[fm][fn][half_ * 2 + 0] + b0) * scale;
                float v1 = (acc[fm][fn][half_ * 2 + 1] + b1) * scale;
                half2 hi = __floats2half2_rn(v0, v1);
                size_t idx = (((size_t)bb * NHEAD + hh) * SLEN + ss) * DKH + ddw;
                *(half2*)(Hh + idx) = hi;
                if (z < 2) {
                    half2 lo = __floats2half2_rn(v0 - __low2float(hi), v1 - __high2float(hi));
                    *(half2*)(Hl + idx) = lo;
                }
            }
        }
    }
}

// ---------------- output projection -------------------------------------------
__global__ __launch_bounds__(256, 2) void outproj_tf32_kernel(
    const float* __restrict__ Bb, float* __restrict__ Out)
{
    const uint32_t* W = g_Wt + (size_t)3 * DMODEL * DMODEL;
    const int m0 = blockIdx.y * 128, n0 = blockIdx.x * 128;
    float acc[4][4][4];
#pragma unroll
    for (int i = 0; i < 4; i++)
#pragma unroll
        for (int j = 0; j < 4; j++)
#pragma unroll
            for (int t = 0; t < 4; t++) acc[i][j][t] = 0.f;

    gemm_tf32_main(g_AOt, W, m0, n0, acc);

    const int tid  = threadIdx.x;
    const int lane = tid & 31, warp = tid >> 5;
    const int wm = warp >> 2, wn = warp & 3;
    const int g  = lane >> 2, tg = lane & 3;

#pragma unroll
    for (int fn = 0; fn < 4; fn++) {
        const int n = n0 + wn * 32 + fn * 8 + 2 * tg;
        const float b0 = Bb[n], b1 = Bb[n + 1];
#pragma unroll
        for (int fm = 0; fm < 4; fm++) {
#pragma unroll
            for (int half_ = 0; half_ < 2; half_++) {
                const int m = m0 + wm * 64 + fm * 16 + g + half_ * 8;
                *(float2*)(Out + (size_t)m * DMODEL + n) =
                    make_float2(acc[fm][fn][half_ * 2 + 0] + b0,
                                acc[fm][fn][half_ * 2 + 1] + b1);
            }
        }
    }
}

// ============ Flash attention: 128-row tiles, 2-stage, P hi-only, V hi-only ====
// smem per stage (u32): K hi [64][40], K lo [64][40], V hi [64][36]
#define KPITCH 40
#define VPITCH 36
#define ST_KHI 0
#define ST_KLO 2560
#define ST_VHI 5120
#define STAGE_U 7424
#define ATTN_SMEM_BYTES (2 * STAGE_U * 4)     // 59392

__device__ __forceinline__ uint32_t h2u(half2 h) {
    return *reinterpret_cast<uint32_t*>(&h);
}

__device__ __forceinline__ void mma_f16(float c[4], const uint32_t a[4],
                                        uint32_t b0, uint32_t b1) {
    asm volatile(
        "mma.sync.aligned.m16n8k16.row.col.f32.f16.f16.f32 "
        "{%0,%1,%2,%3}, {%4,%5,%6,%7}, {%8,%9}, {%0,%1,%2,%3};"
        : "+f"(c[0]), "+f"(c[1]), "+f"(c[2]), "+f"(c[3])
        : "r"(a[0]), "r"(a[1]), "r"(a[2]), "r"(a[3]), "r"(b0), "r"(b1));
}

__global__ __launch_bounds__(256, 2) void attn_hmma_kernel() {
    extern __shared__ uint32_t smu[];

    const int qb = 15 - blockIdx.x;            // long CTAs first
    const int bh = blockIdx.y;
    const size_t base = (size_t)bh * SLEN * DKH;
    const __half* Khg = g_Kh + base;
    const __half* Klg = g_Kl + base;
    const __half* Vhg = g_Vh + base;

    const int tid  = threadIdx.x;
    const int lane = tid & 31, warp = tid >> 5;
    const int g  = lane >> 2, tg = lane & 3;
    const int row0 = warp * 16;
    const uint32_t sb = smem_u32(smu);

    // per-tile loads: K hi/lo = 1024 cp16, V hi = 512 cp16 -> 6 per thread
#define ATTN_ISSUE(kb_, s_)                                                         \
    do {                                                                            \
        _Pragma("unroll")                                                           \
        for (int _j = 0; _j < 4; _j++) {                                            \
            int _t = tid + _j * 256;          /* 0..1023: K hi/lo */                \
            int _row = _t >> 4;                                                     \
            int _ch = _t & 15;                                                      \
            int _c7 = _ch & 7;                                                      \
            const __half* _ks = ((_ch < 8) ? Khg : Klg)                             \
                                + (size_t)((kb_) * 64 + _row) * DKH + _c7 * 8;      \
            cp16(sb + (uint32_t)((s_) * STAGE_U + ((_ch < 8) ? ST_KHI : ST_KLO)     \
                                  + _row * KPITCH + _c7 * 4) * 4, _ks);             \
        }                                                                           \
        _Pragma("unroll")                                                           \
        for (int _j = 0; _j < 2; _j++) {                                            \
            int _t = tid + _j * 256;          /* 0..511: V hi */                    \
            int _row = _t >> 3;                                                     \
            int _c7 = _t & 7;                                                       \
            const __half* _vs = Vhg + (size_t)((kb_) * 64 + _row) * DKH + _c7 * 8;  \
            cp16(sb + (uint32_t)((s_) * STAGE_U + ST_VHI                            \
                                  + _row * VPITCH + _c7 * 4) * 4, _vs);             \
        }                                                                           \
    } while (0)

    ATTN_ISSUE(0, 0); CP_COMMIT();
    ATTN_ISSUE(1, 1); CP_COMMIT();

    // ---- Q fragments -> registers (pair-permuted global, LDG.64) ----
    uint32_t qh[4][4], ql[4][4];
    {
        const uint32_t* Qg  = (const uint32_t*)g_Qh + (base >> 1)
                              + (size_t)(qb * 128 + row0 + g) * 32;
        const uint32_t* Qgl = (const uint32_t*)g_Ql + (base >> 1)
                              + (size_t)(qb * 128 + row0 + g) * 32;
#pragma unroll
        for (int ks = 0; ks < 4; ks++) {
            uint2 a0 = *(const uint2*)(Qg + ks * 8 + 2 * tg);
            uint2 a1 = *(const uint2*)(Qg + 8 * 32 + ks * 8 + 2 * tg);
            qh[ks][0] = a0.x; qh[ks][1] = a1.x; qh[ks][2] = a0.y; qh[ks][3] = a1.y;
            uint2 b0 = *(const uint2*)(Qgl + ks * 8 + 2 * tg);
            uint2 b1 = *(const uint2*)(Qgl + 8 * 32 + ks * 8 + 2 * tg);
            ql[ks][0] = b0.x; ql[ks][1] = b1.x; ql[ks][2] = b0.y; ql[ks][3] = b1.y;
        }
    }

    float acc_o[8][4];
#pragma unroll
    for (int j = 0; j < 8; j++)
#pragma unroll
        for (int t = 0; t < 4; t++) acc_o[j][t] = 0.f;
    float m_run[2] = {-1.0e30f, -1.0e30f};
    float l_run[2] = {0.f, 0.f};

    const int ntiles = 2 * (qb + 1);
    for (int kb = 0; kb < ntiles; kb++) {
        CP_WAIT(1);
        __syncthreads();

        const int s = kb & 1;
        const uint32_t* Khi_s = smu + s * STAGE_U + ST_KHI;
        const uint32_t* Klo_s = smu + s * STAGE_U + ST_KLO;
        const uint32_t vhiB = sb + (uint32_t)(s * STAGE_U + ST_VHI) * 4;

        const bool active = (kb * 64 <= qb * 128 + row0 + 15);

        if (active) {
            // ---- S = Q K^T (3-term split) ----
            float s_acc[8][4];
#pragma unroll
            for (int j = 0; j < 8; j++)
#pragma unroll
                for (int t = 0; t < 4; t++) s_acc[j][t] = 0.f;

#pragma unroll
            for (int ks = 0; ks < 4; ks++) {
#pragma unroll
                for (int fn = 0; fn < 8; fn++) {
                    const int o = (fn * 8 + g) * KPITCH + ks * 8 + 2 * tg;
                    uint2 bh = *(const uint2*)(Khi_s + o);
                    uint2 bl = *(const uint2*)(Klo_s + o);
                    mma_f16(s_acc[fn], qh[ks], bh.x, bh.y);
                    mma_f16(s_acc[fn], qh[ks], bl.x, bl.y);
                    mma_f16(s_acc[fn], ql[ks], bh.x, bh.y);
                }
            }

            // ---- mask + online softmax (base-2) + pack P (hi only) ----
            uint32_t php[8][2];
            const bool diag = (kb >= 2 * qb);
#pragma unroll
            for (int h = 0; h < 2; h++) {
                if (diag) {
                    int row = qb * 128 + row0 + g + 8 * h;
#pragma unroll
                    for (int fn = 0; fn < 8; fn++) {
                        int col = kb * 64 + fn * 8 + 2 * tg;
                        if (col > row)     s_acc[fn][h * 2 + 0] = -1.0e30f;
                        if (col + 1 > row) s_acc[fn][h * 2 + 1] = -1.0e30f;
                    }
                }
                float mx = s_acc[0][h * 2];
#pragma unroll
                for (int fn = 0; fn < 8; fn++) {
                    mx = fmaxf(mx, s_acc[fn][h * 2 + 0]);
                    mx = fmaxf(mx, s_acc[fn][h * 2 + 1]);
                }
                mx = fmaxf(mx, __shfl_xor_sync(0xffffffffu, mx, 1));
                mx = fmaxf(mx, __shfl_xor_sync(0xffffffffu, mx, 2));
                float mn   = fmaxf(m_run[h], mx);
                float corr = exp2f(m_run[h] - mn);
                float rs = 0.f;
#pragma unroll
                for (int fn = 0; fn < 8; fn++) {
                    float p0 = exp2f(s_acc[fn][h * 2 + 0] - mn);
                    float p1 = exp2f(s_acc[fn][h * 2 + 1] - mn);
                    rs += p0 + p1;
                    php[fn][h] = h2u(__floats2half2_rn(p0, p1));
                }
                rs += __shfl_xor_sync(0xffffffffu, rs, 1);
                rs += __shfl_xor_sync(0xffffffffu, rs, 2);
                l_run[h] = l_run[h] * corr + rs;
                m_run[h] = mn;
#pragma unroll
                for (int fn = 0; fn < 8; fn++) {
                    acc_o[fn][h * 2 + 0] *= corr;
                    acc_o[fn][h * 2 + 1] *= corr;
                }
            }

            // ---- O += P V (P hi-only, V hi-only) ----
#pragma unroll
            for (int ks = 0; ks < 4; ks++) {
                uint32_t ahi[4] = { php[2 * ks][0], php[2 * ks][1],
                                    php[2 * ks + 1][0], php[2 * ks + 1][1] };
                const int vrow = ks * 16 + (lane & 15);
                const uint32_t abH = vhiB + (uint32_t)(vrow * VPITCH) * 4;
#pragma unroll
                for (int fn = 0; fn < 8; fn++) {
                    uint2 bh = ldsm_x2_trans(abH + fn * 16);
                    mma_f16(acc_o[fn], ahi, bh.x, bh.y);
                }
            }
        }

        __syncthreads();
        if (kb + 2 < ntiles) ATTN_ISSUE(kb + 2, s);
        CP_COMMIT();
    }
#undef ATTN_ISSUE

    // ---- normalize + write tf32 pair-permuted AO (R9 permutation) ----
    const int bb = bh >> 4, hh = bh & 15;
    const int kk0 = 2 * tg, kk1 = 2 * tg + 1;
    const int p0 = ((kk0 & 3) << 1) | (kk0 >> 2);
    const int p1 = ((kk1 & 3) << 1) | (kk1 >> 2);
#pragma unroll
    for (int h = 0; h < 2; h++) {
        float invl = 1.0f / l_run[h];
        int row = qb * 128 + row0 + g + 8 * h;
        uint32_t* dst = g_AOt + ((size_t)bb * SLEN + row) * DMODEL + hh * DKH;
#pragma unroll
        for (int fn = 0; fn < 8; fn++) {
            dst[fn * 8 + p0] = f2tf32(acc_o[fn][h * 2 + 0] * invl);
            dst[fn * 8 + p1] = f2tf32(acc_o[fn][h * 2 + 1] * invl);
        }
    }
}

// ---------------- launch -------------------------------------------------------
extern "C" void kernel_launch(void* const* d_in, const int* in_sizes, int n_in,
                              void* d_out, int out_size) {
    const float* q  = (const float*)d_in[0];
    const float* k  = (const float*)d_in[1];
    const float* v  = (const float*)d_in[2];
    // d_in[3] = mask (int32 tril) — causal, applied analytically
    const float* wq = (const float*)d_in[4];
    const float* bq = (const float*)d_in[5];
    const float* wk = (const float*)d_in[6];
    const float* bk = (const float*)d_in[7];
    const float* wv = (const float*)d_in[8];
    const float* bv = (const float*)d_in[9];
    const float* wo = (const float*)d_in[10];
    const float* bo = (const float*)d_in[11];
    float* out = (float*)d_out;

    cudaFuncSetAttribute(qkv_tf32_kernel, cudaFuncAttributeMaxDynamicSharedMemorySize, GEMM_SMEM);
    cudaFuncSetAttribute(outproj_tf32_kernel, cudaFuncAttributeMaxDynamicSharedMemorySize, GEMM_SMEM);
    cudaFuncSetAttribute(attn_hmma_kernel, cudaFuncAttributeMaxDynamicSharedMemorySize, ATTN_SMEM_BYTES);

    conv_all_kernel<<<14336, 256>>>(q, k, v, wq, wk, wv, wo);

    qkv_tf32_kernel<<<dim3(DMODEL / 128, MTOT / 128, 3), 256, GEMM_SMEM>>>(bq, bk, bv);

    attn_hmma_kernel<<<dim3(SLEN / 128, NB * NHEAD), 256, ATTN_SMEM_BYTES>>>();

    outproj_tf32_kernel<<<dim3(DMODEL / 128, MTOT / 128), 256, GEMM_SMEM>>>(bo, out);
}